// round 3
// baseline (speedup 1.0000x reference)
#include <cuda_runtime.h>

// Problem constants
#define Bn 8
#define Cn 4
#define Hn 64
#define Wn 2048
#define HWn (Hn * Wn)          // 131072
#define CHWn (Cn * HWn)        // 524288

// Tile config
#define TX 128
#define TY 8
#define HX (TX + 4)            // 132 (halo +-2 in W)
#define HY (TY + 2)            // 10  (halo +-1 in H)
#define HALO (HX * HY)         // 1320
#define NTHREADS 256
#define XPB 4                  // pixels per thread along x

// Gaussian smoothness weights: exp(-(dh^2+dw^2)/(2*0.9^2)), center = 0
#define W1 0.53940751f   // d2 = 1
#define W2 0.29096046f   // d2 = 2
#define W4 0.08465798f   // d2 = 4
#define W5 0.04566517f   // d2 = 5

// C2 = -1/(2*0.015^2) * log2(e)  (exp(x) == exp2(x*log2e))
#define C2f      (-3206.0005353f)
#define NEG2C2f  (6412.0010706f)     // -2 * C2
#define L2Ef     (1.4426950408889634f)
#define MASK_BIG (1.0e9f)

// Ping-pong scratch, packed float4 per pixel (allocation forbidden -> device globals)
__device__ float4 g_scratchA[Bn * HWn];
__device__ float4 g_scratchB[Bn * HWn];

// ---- packed f32x2 helpers (sm_10x) ----
__device__ __forceinline__ unsigned long long pk2(float lo, float hi) {
    unsigned long long r;
    asm("mov.b64 %0, {%1, %2};" : "=l"(r) : "f"(lo), "f"(hi));
    return r;
}
__device__ __forceinline__ void upk2(unsigned long long v, float& lo, float& hi) {
    asm("mov.b64 {%0, %1}, %2;" : "=f"(lo), "=f"(hi) : "l"(v));
}
__device__ __forceinline__ unsigned long long ffma2(unsigned long long a,
                                                    unsigned long long b,
                                                    unsigned long long c) {
    unsigned long long d;
    asm("fma.rn.f32x2 %0, %1, %2, %3;" : "=l"(d) : "l"(a), "l"(b), "l"(c));
    return d;
}
__device__ __forceinline__ float ex2(float x) {
    float r;
    asm("ex2.approx.ftz.f32 %0, %1;" : "=f"(r) : "f"(x));
    return r;
}

template<bool IN_PACKED, bool OUT_PACKED>
__global__ __launch_bounds__(NTHREADS)
void crf_iter(const float*  __restrict__ QinPlanar,
              const float4* __restrict__ QinPacked,
              const float*  __restrict__ unary,
              const float*  __restrict__ xyz,
              const float*  __restrict__ mask,
              const float*  __restrict__ wapp,
              const float*  __restrict__ wsmo,
              const float*  __restrict__ compat,
              float*        __restrict__ OutPlanar,
              float4*       __restrict__ OutPacked)
{
    __shared__ float4 sQ[HALO];   // softmaxed probs (p0,p1,p2,p3)
    __shared__ float4 sG[HALO];   // (x, y, z, |xyz|^2*C2 + (m-1)*BIG)

    const int b   = blockIdx.z;
    const int ty0 = blockIdx.y * TY;
    const int tx0 = blockIdx.x * TX;
    const int tid = threadIdx.x;

    const float* __restrict__ Xb = xyz  + b * 3 * HWn;
    const float* __restrict__ Mb = mask + b * HWn;

    // ---- Phase 1: load halo tile, softmax over C, fold geometry ----
    for (int i = tid; i < HALO; i += NTHREADS) {
        const int hy = i / HX;
        const int hx = i - hy * HX;
        const int gy = ty0 + hy - 1;
        const int gx = tx0 + hx - 2;
        float4 sq = make_float4(0.f, 0.f, 0.f, 0.f);
        float4 sg = make_float4(0.f, 0.f, 0.f, -MASK_BIG);
        if (gy >= 0 && gy < Hn && gx >= 0 && gx < Wn) {
            const int g = gy * Wn + gx;
            float q0, q1, q2, q3;
            if (IN_PACKED) {
                const float4 q = QinPacked[b * HWn + g];
                q0 = q.x; q1 = q.y; q2 = q.z; q3 = q.w;
            } else {
                const float* Qb = QinPlanar + b * CHWn;
                q0 = Qb[g];
                q1 = Qb[g + HWn];
                q2 = Qb[g + 2 * HWn];
                q3 = Qb[g + 3 * HWn];
            }
            const float mx = fmaxf(fmaxf(q0, q1), fmaxf(q2, q3));
            float p0 = ex2((q0 - mx) * L2Ef);
            float p1 = ex2((q1 - mx) * L2Ef);
            float p2 = ex2((q2 - mx) * L2Ef);
            float p3 = ex2((q3 - mx) * L2Ef);
            const float inv = __fdividef(1.0f, p0 + p1 + p2 + p3);
            sq.x = p0 * inv; sq.y = p1 * inv; sq.z = p2 * inv; sq.w = p3 * inv;

            const float x = Xb[g];
            const float y = Xb[g + HWn];
            const float z = Xb[g + 2 * HWn];
            const float m = Mb[g];
            float nrm = x * x;
            nrm = fmaf(y, y, nrm);
            nrm = fmaf(z, z, nrm);
            sg.x = x; sg.y = y; sg.z = z;
            // |n|^2*C2 + (m-1)*BIG  (m in {0,1}; masked -> arg <= -1e9 -> exp2 = 0)
            sg.w = fmaf(nrm, C2f, fmaf(m, MASK_BIG, -MASK_BIG));
        }
        sQ[i] = sq;
        sG[i] = sg;
    }

    // Per-channel weights + compatibility matrix (uniform)
    const float wa0 = wapp[0], wa1 = wapp[1], wa2 = wapp[2], wa3 = wapp[3];
    const float ws0 = wsmo[0], ws1 = wsmo[1], ws2 = wsmo[2], ws3 = wsmo[3];
    const float c00 = compat[0],  c01 = compat[1],  c02 = compat[2],  c03 = compat[3];
    const float c10 = compat[4],  c11 = compat[5],  c12 = compat[6],  c13 = compat[7];
    const float c20 = compat[8],  c21 = compat[9],  c22 = compat[10], c23 = compat[11];
    const float c30 = compat[12], c31 = compat[13], c32 = compat[14], c33 = compat[15];

    __syncthreads();

    // Packed tap weights (only 4 distinct values)
    const unsigned long long w1p = pk2(W1, W1);
    const unsigned long long w2p = pk2(W2, W2);
    const unsigned long long w4p = pk2(W4, W4);
    const unsigned long long w5p = pk2(W5, W5);

    // ---- Phase 2: x-register-blocked fused 14-tap conv + appearance ----
    // Thread handles XPB=4 consecutive x pixels. Union of their tap windows:
    // 3 rows x (XPB+4)=8 cols = 24 smem points, each loaded ONCE.
    const int ty = tid >> 5;            // 0..7   (tile row)
    const int lx = tid & 31;            // 0..31  (x group)
    const int x0 = lx * XPB;            // pixel-0 x within tile
    const int base = (ty + 1) * HX + (x0 + 2);   // smem index of pixel 0

    // Anchors (pre-scaled)
    float axs[XPB], ays[XPB], azs[XPB], na[XPB], mC[XPB];
    #pragma unroll
    for (int i = 0; i < XPB; ++i) {
        const float4 ga = sG[base + i];
        axs[i] = ga.x * NEG2C2f;
        ays[i] = ga.y * NEG2C2f;
        azs[i] = ga.z * NEG2C2f;
        na[i]  = ga.w;
        mC[i]  = (ga.w > -1.0e8f) ? 1.0f : 0.0f;
    }

    unsigned long long s01[XPB], s23[XPB], a01[XPB], a23[XPB];
    #pragma unroll
    for (int i = 0; i < XPB; ++i) { s01[i] = s23[i] = a01[i] = a23[i] = 0ull; }

    #pragma unroll
    for (int r = -1; r <= 1; ++r) {
        #pragma unroll
        for (int c = 0; c < XPB + 4; ++c) {
            const int nb = base + r * HX + (c - 2);
            const float4 gn = sG[nb];
            const ulonglong2 q2 = *reinterpret_cast<const ulonglong2*>(&sQ[nb]);
            #pragma unroll
            for (int i = 0; i < XPB; ++i) {
                const int dw = c - 2 - i;
                if (dw < -2 || dw > 2) continue;        // outside this pixel's window
                if (r == 0 && dw == 0) continue;        // center hole
                const int d2 = r * r + dw * dw;         // 1,2,4,5
                const unsigned long long wtp =
                    (d2 == 1) ? w1p : (d2 == 2) ? w2p : (d2 == 4) ? w4p : w5p;
                const float arg = fmaf(gn.x, axs[i],
                                  fmaf(gn.y, ays[i],
                                  fmaf(gn.z, azs[i], gn.w + na[i])));
                const float bm = ex2(arg);              // beta * m_nb
                const unsigned long long bm2 = pk2(bm, bm);
                s01[i] = ffma2(wtp, q2.x, s01[i]);
                s23[i] = ffma2(wtp, q2.y, s23[i]);
                a01[i] = ffma2(bm2, q2.x, a01[i]);
                a23[i] = ffma2(bm2, q2.y, a23[i]);
            }
        }
    }

    // ---- Epilogue: weights, compat matvec, residual vs unary ----
    const int gy  = ty0 + ty;
    const int gx0 = tx0 + x0;
    const int g0  = gy * Wn + gx0;              // pixel-0 flat HW index
    const int gg0 = b * CHWn + g0;

    const float4 u0v = *reinterpret_cast<const float4*>(unary + gg0);
    const float4 u1v = *reinterpret_cast<const float4*>(unary + gg0 + HWn);
    const float4 u2v = *reinterpret_cast<const float4*>(unary + gg0 + 2 * HWn);
    const float4 u3v = *reinterpret_cast<const float4*>(unary + gg0 + 3 * HWn);
    const float u0a[XPB] = {u0v.x, u0v.y, u0v.z, u0v.w};
    const float u1a[XPB] = {u1v.x, u1v.y, u1v.z, u1v.w};
    const float u2a[XPB] = {u2v.x, u2v.y, u2v.z, u2v.w};
    const float u3a[XPB] = {u3v.x, u3v.y, u3v.z, u3v.w};

    float o0[XPB], o1[XPB], o2[XPB], o3[XPB];

    #pragma unroll
    for (int i = 0; i < XPB; ++i) {
        float s0, s1, s2, s3, a0, a1, a2, a3;
        upk2(s01[i], s0, s1); upk2(s23[i], s2, s3);
        upk2(a01[i], a0, a1); upk2(a23[i], a2, a3);

        const float m = mC[i];
        a0 *= m; a1 *= m; a2 *= m; a3 *= m;
        const float wk0 = s0 * fmaf(wa0, a0, ws0);
        const float wk1 = s1 * fmaf(wa1, a1, ws1);
        const float wk2 = s2 * fmaf(wa2, a2, ws2);
        const float wk3 = s3 * fmaf(wa3, a3, ws3);

        const float pw0 = c00 * wk0 + c01 * wk1 + c02 * wk2 + c03 * wk3;
        const float pw1 = c10 * wk0 + c11 * wk1 + c12 * wk2 + c13 * wk3;
        const float pw2 = c20 * wk0 + c21 * wk1 + c22 * wk2 + c23 * wk3;
        const float pw3 = c30 * wk0 + c31 * wk1 + c32 * wk2 + c33 * wk3;

        o0[i] = u0a[i] - pw0;
        o1[i] = u1a[i] - pw1;
        o2[i] = u2a[i] - pw2;
        o3[i] = u3a[i] - pw3;
    }

    if (OUT_PACKED) {
        float4* dst = OutPacked + b * HWn + g0;
        #pragma unroll
        for (int i = 0; i < XPB; ++i)
            dst[i] = make_float4(o0[i], o1[i], o2[i], o3[i]);
    } else {
        *reinterpret_cast<float4*>(OutPlanar + gg0)            = make_float4(o0[0], o0[1], o0[2], o0[3]);
        *reinterpret_cast<float4*>(OutPlanar + gg0 + HWn)      = make_float4(o1[0], o1[1], o1[2], o1[3]);
        *reinterpret_cast<float4*>(OutPlanar + gg0 + 2 * HWn)  = make_float4(o2[0], o2[1], o2[2], o2[3]);
        *reinterpret_cast<float4*>(OutPlanar + gg0 + 3 * HWn)  = make_float4(o3[0], o3[1], o3[2], o3[3]);
    }
}

extern "C" void kernel_launch(void* const* d_in, const int* in_sizes, int n_in,
                              void* d_out, int out_size)
{
    const float* unary  = (const float*)d_in[0];
    const float* xyz    = (const float*)d_in[1];
    const float* mask   = (const float*)d_in[2];
    const float* wapp   = (const float*)d_in[3];
    const float* wsmo   = (const float*)d_in[4];
    const float* compat = (const float*)d_in[5];
    float* out = (float*)d_out;

    float4* sA = nullptr;
    float4* sB = nullptr;
    cudaGetSymbolAddress((void**)&sA, g_scratchA);
    cudaGetSymbolAddress((void**)&sB, g_scratchB);

    dim3 grid(Wn / TX, Hn / TY, Bn);
    dim3 block(NTHREADS);

    // iter 1: unary(planar) -> scratchA(packed)
    crf_iter<false, true><<<grid, block>>>(unary, nullptr, unary, xyz, mask,
                                           wapp, wsmo, compat, nullptr, sA);
    // iter 2: scratchA(packed) -> scratchB(packed)
    crf_iter<true, true><<<grid, block>>>(nullptr, sA, unary, xyz, mask,
                                          wapp, wsmo, compat, nullptr, sB);
    // iter 3: scratchB(packed) -> out(planar)
    crf_iter<true, false><<<grid, block>>>(nullptr, sB, unary, xyz, mask,
                                           wapp, wsmo, compat, out, nullptr);
}

// round 4
// speedup vs baseline: 1.5312x; 1.5312x over previous
#include <cuda_runtime.h>

// Problem constants
#define Bn 8
#define Cn 4
#define Hn 64
#define Wn 2048
#define HWn (Hn * Wn)          // 131072
#define CHWn (Cn * HWn)        // 524288

// Tile config
#define TX 128
#define TY 8
#define HX (TX + 4)            // 132 (halo +-2 in W)
#define HY (TY + 2)            // 10  (halo +-1 in H)
#define HALO (HX * HY)         // 1320
#define NTHREADS 256

// Gaussian smoothness weights: exp(-(dh^2+dw^2)/(2*0.9^2)), center = 0
#define W1 0.53940751f   // d2 = 1
#define W2 0.29096046f   // d2 = 2
#define W4 0.08465798f   // d2 = 4
#define W5 0.04566517f   // d2 = 5

// C2 = -1/(2*0.015^2) * log2(e)  (exp(x) == exp2(x*log2e))
#define C2f      (-3206.0005353f)
#define NEG2C2f  (6412.0010706f)     // -2 * C2
#define L2Ef     (1.4426950408889634f)
#define MASK_BIG (1.0e9f)
#define SKIP_THR (-40.0f)            // exp2(-40) ~ 9e-13 -> dead

// Ping-pong scratch, packed float4 per pixel (allocation forbidden -> device globals)
__device__ float4 g_scratchA[Bn * HWn];
__device__ float4 g_scratchB[Bn * HWn];

// ---- packed f32x2 helpers (sm_10x) ----
__device__ __forceinline__ unsigned long long pk2(float lo, float hi) {
    unsigned long long r;
    asm("mov.b64 %0, {%1, %2};" : "=l"(r) : "f"(lo), "f"(hi));
    return r;
}
__device__ __forceinline__ void upk2(unsigned long long v, float& lo, float& hi) {
    asm("mov.b64 {%0, %1}, %2;" : "=f"(lo), "=f"(hi) : "l"(v));
}
__device__ __forceinline__ unsigned long long ffma2(unsigned long long a,
                                                    unsigned long long b,
                                                    unsigned long long c) {
    unsigned long long d;
    asm("fma.rn.f32x2 %0, %1, %2, %3;" : "=l"(d) : "l"(a), "l"(b), "l"(c));
    return d;
}
__device__ __forceinline__ float ex2(float x) {
    float r;
    asm("ex2.approx.ftz.f32 %0, %1;" : "=f"(r) : "f"(x));
    return r;
}

template<bool IN_PACKED, bool OUT_PACKED>
__global__ __launch_bounds__(NTHREADS)
void crf_iter(const float*  __restrict__ QinPlanar,
              const float4* __restrict__ QinPacked,
              const float*  __restrict__ unary,
              const float*  __restrict__ xyz,
              const float*  __restrict__ mask,
              const float*  __restrict__ wapp,
              const float*  __restrict__ wsmo,
              const float*  __restrict__ compat,
              float*        __restrict__ OutPlanar,
              float4*       __restrict__ OutPacked)
{
    __shared__ float4 sQ[HALO];   // softmaxed probs (p0,p1,p2,p3)
    __shared__ float4 sG[HALO];   // (x, y, z, |xyz|^2*C2 + (m-1)*BIG)

    const int b   = blockIdx.z;
    const int ty0 = blockIdx.y * TY;
    const int tx0 = blockIdx.x * TX;
    const int tid = threadIdx.x;

    const float* __restrict__ Xb = xyz  + b * 3 * HWn;
    const float* __restrict__ Mb = mask + b * HWn;

    // ---- Phase 1: load halo tile, softmax over C, fold geometry ----
    for (int i = tid; i < HALO; i += NTHREADS) {
        const int hy = i / HX;
        const int hx = i - hy * HX;
        const int gy = ty0 + hy - 1;
        const int gx = tx0 + hx - 2;
        float4 sq = make_float4(0.f, 0.f, 0.f, 0.f);
        float4 sg = make_float4(0.f, 0.f, 0.f, -MASK_BIG);
        if (gy >= 0 && gy < Hn && gx >= 0 && gx < Wn) {
            const int g = gy * Wn + gx;
            float q0, q1, q2, q3;
            if (IN_PACKED) {
                const float4 q = QinPacked[b * HWn + g];
                q0 = q.x; q1 = q.y; q2 = q.z; q3 = q.w;
            } else {
                const float* Qb = QinPlanar + b * CHWn;
                q0 = Qb[g];
                q1 = Qb[g + HWn];
                q2 = Qb[g + 2 * HWn];
                q3 = Qb[g + 3 * HWn];
            }
            const float mx = fmaxf(fmaxf(q0, q1), fmaxf(q2, q3));
            float p0 = ex2((q0 - mx) * L2Ef);
            float p1 = ex2((q1 - mx) * L2Ef);
            float p2 = ex2((q2 - mx) * L2Ef);
            float p3 = ex2((q3 - mx) * L2Ef);
            const float inv = __fdividef(1.0f, p0 + p1 + p2 + p3);
            sq.x = p0 * inv; sq.y = p1 * inv; sq.z = p2 * inv; sq.w = p3 * inv;

            const float x = Xb[g];
            const float y = Xb[g + HWn];
            const float z = Xb[g + 2 * HWn];
            const float m = Mb[g];
            float nrm = x * x;
            nrm = fmaf(y, y, nrm);
            nrm = fmaf(z, z, nrm);
            sg.x = x; sg.y = y; sg.z = z;
            // |n|^2*C2 + (m-1)*BIG  (m in {0,1}; masked -> arg <= -1e9 -> exp2 = 0)
            sg.w = fmaf(nrm, C2f, fmaf(m, MASK_BIG, -MASK_BIG));
        }
        sQ[i] = sq;
        sG[i] = sg;
    }

    // Per-channel weights + compatibility matrix (uniform)
    const float wa0 = wapp[0], wa1 = wapp[1], wa2 = wapp[2], wa3 = wapp[3];
    const float ws0 = wsmo[0], ws1 = wsmo[1], ws2 = wsmo[2], ws3 = wsmo[3];
    const float c00 = compat[0],  c01 = compat[1],  c02 = compat[2],  c03 = compat[3];
    const float c10 = compat[4],  c11 = compat[5],  c12 = compat[6],  c13 = compat[7];
    const float c20 = compat[8],  c21 = compat[9],  c22 = compat[10], c23 = compat[11];
    const float c30 = compat[12], c31 = compat[13], c32 = compat[14], c33 = compat[15];

    __syncthreads();

    // Packed tap weights (only 4 distinct values)
    const unsigned long long w1p = pk2(W1, W1);
    const unsigned long long w2p = pk2(W2, W2);
    const unsigned long long w4p = pk2(W4, W4);
    const unsigned long long w5p = pk2(W5, W5);

    // ---- Phase 2: fused taps; appearance path gated by warp vote ----
    #pragma unroll
    for (int k = 0; k < (TX * TY) / NTHREADS; ++k) {
        const int p  = tid + k * NTHREADS;
        const int ty = p / TX;
        const int tx = p - ty * TX;
        const int base = (ty + 1) * HX + (tx + 2);

        const float4 ga = sG[base];
        const float axs = ga.x * NEG2C2f;
        const float ays = ga.y * NEG2C2f;
        const float azs = ga.z * NEG2C2f;
        const float na  = ga.w;                          // |a|^2*C2 (mask-folded)
        const float mC  = (na > -1.0e8f) ? 1.0f : 0.0f;  // recover center mask

        unsigned long long s01 = 0ull, s23 = 0ull;   // smoothness conv accum
        unsigned long long a01 = 0ull, a23 = 0ull;   // appearance accum

        const int offs[14] = {
            -HX - 2, -HX - 1, -HX, -HX + 1, -HX + 2,
                  -2,      -1,           1,       2,
             HX - 2,  HX - 1,  HX,  HX + 1,  HX + 2
        };
        const unsigned long long wtp[14] = {
            w5p, w2p, w1p, w2p, w5p,
            w4p, w1p, w1p, w4p,
            w5p, w2p, w1p, w2p, w5p
        };

        float args[14];
        float maxa = -MASK_BIG;

        // Pass A: smoothness conv + beta args (no exp)
        #pragma unroll
        for (int t = 0; t < 14; ++t) {
            const int nb = base + offs[t];
            const float4 gn = sG[nb];
            const float arg = fmaf(gn.x, axs,
                              fmaf(gn.y, ays,
                              fmaf(gn.z, azs, gn.w + na)));
            args[t] = arg;
            maxa = fmaxf(maxa, arg);
            const ulonglong2 q2 = *reinterpret_cast<const ulonglong2*>(&sQ[nb]);
            s01 = ffma2(wtp[t], q2.x, s01);
            s23 = ffma2(wtp[t], q2.y, s23);
        }

        // Pass B (rare, ~8% of warps): appearance accumulation
        if (__any_sync(0xFFFFFFFFu, maxa > SKIP_THR)) {
            #pragma unroll
            for (int t = 0; t < 14; ++t) {
                const float bm = ex2(args[t]);           // beta * m_nb
                const ulonglong2 q2 =
                    *reinterpret_cast<const ulonglong2*>(&sQ[base + offs[t]]);
                const unsigned long long bm2 = pk2(bm, bm);
                a01 = ffma2(bm2, q2.x, a01);
                a23 = ffma2(bm2, q2.y, a23);
            }
        }

        float s0, s1, s2, s3, a0, a1, a2, a3;
        upk2(s01, s0, s1); upk2(s23, s2, s3);
        upk2(a01, a0, a1); upk2(a23, a2, a3);

        // exp_app = a * m_center ; weighted_k = s * (ws + wa * exp_app)
        a0 *= mC; a1 *= mC; a2 *= mC; a3 *= mC;
        const float wk0 = s0 * fmaf(wa0, a0, ws0);
        const float wk1 = s1 * fmaf(wa1, a1, ws1);
        const float wk2 = s2 * fmaf(wa2, a2, ws2);
        const float wk3 = s3 * fmaf(wa3, a3, ws3);

        // pairwise[o] = sum_c compat[o][c] * wk[c]
        const float pw0 = c00 * wk0 + c01 * wk1 + c02 * wk2 + c03 * wk3;
        const float pw1 = c10 * wk0 + c11 * wk1 + c12 * wk2 + c13 * wk3;
        const float pw2 = c20 * wk0 + c21 * wk1 + c22 * wk2 + c23 * wk3;
        const float pw3 = c30 * wk0 + c31 * wk1 + c32 * wk2 + c33 * wk3;

        const int g = (ty0 + ty) * Wn + (tx0 + tx);
        const int gg = b * CHWn + g;
        const float u0 = unary[gg];
        const float u1 = unary[gg + HWn];
        const float u2 = unary[gg + 2 * HWn];
        const float u3 = unary[gg + 3 * HWn];

        if (OUT_PACKED) {
            OutPacked[b * HWn + g] = make_float4(u0 - pw0, u1 - pw1, u2 - pw2, u3 - pw3);
        } else {
            OutPlanar[gg]           = u0 - pw0;
            OutPlanar[gg + HWn]     = u1 - pw1;
            OutPlanar[gg + 2 * HWn] = u2 - pw2;
            OutPlanar[gg + 3 * HWn] = u3 - pw3;
        }
    }
}

extern "C" void kernel_launch(void* const* d_in, const int* in_sizes, int n_in,
                              void* d_out, int out_size)
{
    const float* unary  = (const float*)d_in[0];
    const float* xyz    = (const float*)d_in[1];
    const float* mask   = (const float*)d_in[2];
    const float* wapp   = (const float*)d_in[3];
    const float* wsmo   = (const float*)d_in[4];
    const float* compat = (const float*)d_in[5];
    float* out = (float*)d_out;

    float4* sA = nullptr;
    float4* sB = nullptr;
    cudaGetSymbolAddress((void**)&sA, g_scratchA);
    cudaGetSymbolAddress((void**)&sB, g_scratchB);

    dim3 grid(Wn / TX, Hn / TY, Bn);
    dim3 block(NTHREADS);

    // iter 1: unary(planar) -> scratchA(packed)
    crf_iter<false, true><<<grid, block>>>(unary, nullptr, unary, xyz, mask,
                                           wapp, wsmo, compat, nullptr, sA);
    // iter 2: scratchA(packed) -> scratchB(packed)
    crf_iter<true, true><<<grid, block>>>(nullptr, sA, unary, xyz, mask,
                                          wapp, wsmo, compat, nullptr, sB);
    // iter 3: scratchB(packed) -> out(planar)
    crf_iter<true, false><<<grid, block>>>(nullptr, sB, unary, xyz, mask,
                                           wapp, wsmo, compat, out, nullptr);
}

// round 5
// speedup vs baseline: 1.6016x; 1.0460x over previous
#include <cuda_runtime.h>

// Problem constants
#define Bn 8
#define Hn 64
#define Wn 2048
#define HWn (Hn * Wn)          // 131072
#define CHWn (4 * HWn)         // 524288

// Tile config
#define TX 128
#define TY 8
#define HX (TX + 4)            // 132
#define HY (TY + 2)            // 10
#define HALO (HX * HY)         // 1320
#define NTHREADS 256

// Gaussian smoothness weights: exp(-(dh^2+dw^2)/(2*0.9^2)), center = 0
#define W1 0.53940751f   // d2 = 1
#define W2 0.29096046f   // d2 = 2
#define W4 0.08465798f   // d2 = 4
#define W5 0.04566517f   // d2 = 5

// C2 = -1/(2*0.015^2) * log2(e)
#define C2f      (-3206.0005353f)
#define NEG2C2f  (6412.0010706f)
#define L2Ef     (1.4426950408889634f)
#define MASK_BIG (1.0e9f)
#define SKIP_THR (-40.0f)      // exp2(-40) ~ 9e-13 -> dead

// Scratch (allocation forbidden -> device globals; zero-init, not in cubin)
__device__ float4        g_scratchA[Bn * HWn];
__device__ float4        g_scratchB[Bn * HWn];
__device__ unsigned char g_alive[Bn * HWn];       // 1 MB, per-pixel flag
__device__ float         g_beta[Bn * HWn * 14];   // sparse: only alive pixels touched

// ---- packed f32x2 helpers (sm_10x) ----
__device__ __forceinline__ unsigned long long pk2(float lo, float hi) {
    unsigned long long r;
    asm("mov.b64 %0, {%1, %2};" : "=l"(r) : "f"(lo), "f"(hi));
    return r;
}
__device__ __forceinline__ void upk2(unsigned long long v, float& lo, float& hi) {
    asm("mov.b64 {%0, %1}, %2;" : "=f"(lo), "=f"(hi) : "l"(v));
}
__device__ __forceinline__ unsigned long long ffma2(unsigned long long a,
                                                    unsigned long long b,
                                                    unsigned long long c) {
    unsigned long long d;
    asm("fma.rn.f32x2 %0, %1, %2, %3;" : "=l"(d) : "l"(a), "l"(b), "l"(c));
    return d;
}
__device__ __forceinline__ float ex2(float x) {
    float r;
    asm("ex2.approx.ftz.f32 %0, %1;" : "=f"(r) : "f"(x));
    return r;
}

// ============================================================================
// Setup: compute per-pixel alive flag + (rare) exact beta taps. Runs once/call.
// ============================================================================
__global__ __launch_bounds__(NTHREADS)
void crf_setup(const float* __restrict__ xyz,
               const float* __restrict__ mask)
{
    __shared__ float4 sG[HALO];   // (x, y, z, |xyz|^2*C2 + (m-1)*BIG)

    const int b   = blockIdx.z;
    const int ty0 = blockIdx.y * TY;
    const int tx0 = blockIdx.x * TX;
    const int tid = threadIdx.x;

    const float* __restrict__ Xb = xyz  + b * 3 * HWn;
    const float* __restrict__ Mb = mask + b * HWn;

    for (int i = tid; i < HALO; i += NTHREADS) {
        const int hy = i / HX;
        const int hx = i - hy * HX;
        const int gy = ty0 + hy - 1;
        const int gx = tx0 + hx - 2;
        float4 sg = make_float4(0.f, 0.f, 0.f, -MASK_BIG);
        if (gy >= 0 && gy < Hn && gx >= 0 && gx < Wn) {
            const int g = gy * Wn + gx;
            const float x = Xb[g];
            const float y = Xb[g + HWn];
            const float z = Xb[g + 2 * HWn];
            const float m = Mb[g];
            float nrm = x * x;
            nrm = fmaf(y, y, nrm);
            nrm = fmaf(z, z, nrm);
            sg.x = x; sg.y = y; sg.z = z;
            sg.w = fmaf(nrm, C2f, fmaf(m, MASK_BIG, -MASK_BIG));
        }
        sG[i] = sg;
    }
    __syncthreads();

    const int offs[14] = {
        -HX - 2, -HX - 1, -HX, -HX + 1, -HX + 2,
              -2,      -1,           1,       2,
         HX - 2,  HX - 1,  HX,  HX + 1,  HX + 2
    };

    #pragma unroll
    for (int k = 0; k < (TX * TY) / NTHREADS; ++k) {
        const int p  = tid + k * NTHREADS;
        const int ty = p / TX;
        const int tx = p - ty * TX;
        const int base = (ty + 1) * HX + (tx + 2);

        const float4 ga = sG[base];
        const float axs = ga.x * NEG2C2f;
        const float ays = ga.y * NEG2C2f;
        const float azs = ga.z * NEG2C2f;
        const float na  = ga.w;

        float maxa = -MASK_BIG;
        #pragma unroll
        for (int t = 0; t < 14; ++t) {
            const float4 gn = sG[base + offs[t]];
            const float arg = fmaf(gn.x, axs,
                              fmaf(gn.y, ays,
                              fmaf(gn.z, azs, gn.w + na)));
            maxa = fmaxf(maxa, arg);
        }

        // alive only if some beta survives AND center unmasked (exp_app *= m_c)
        const bool alive = (maxa > SKIP_THR) && (na > -1.0e8f);
        const int pix = b * HWn + (ty0 + ty) * Wn + (tx0 + tx);
        g_alive[pix] = alive ? 1 : 0;

        if (alive) {
            #pragma unroll
            for (int t = 0; t < 14; ++t) {
                const float4 gn = sG[base + offs[t]];
                const float arg = fmaf(gn.x, axs,
                                  fmaf(gn.y, ays,
                                  fmaf(gn.z, azs, gn.w + na)));
                g_beta[pix * 14 + t] = ex2(arg);   // beta * m_nb (exact 0 if masked/OOB)
            }
        }
    }
}

// ============================================================================
// One CRF iteration: softmax + smoothness conv; appearance via precomputed beta.
// ============================================================================
template<bool IN_PACKED, bool OUT_PACKED>
__global__ __launch_bounds__(NTHREADS)
void crf_iter(const float*  __restrict__ QinPlanar,
              const float4* __restrict__ QinPacked,
              const float*  __restrict__ unary,
              const float*  __restrict__ wapp,
              const float*  __restrict__ wsmo,
              const float*  __restrict__ compat,
              float*        __restrict__ OutPlanar,
              float4*       __restrict__ OutPacked)
{
    __shared__ float4 sQ[HALO];   // softmaxed probs

    const int b   = blockIdx.z;
    const int ty0 = blockIdx.y * TY;
    const int tx0 = blockIdx.x * TX;
    const int tid = threadIdx.x;

    // ---- Phase 1: softmax halo tile into smem ----
    for (int i = tid; i < HALO; i += NTHREADS) {
        const int hy = i / HX;
        const int hx = i - hy * HX;
        const int gy = ty0 + hy - 1;
        const int gx = tx0 + hx - 2;
        float4 sq = make_float4(0.f, 0.f, 0.f, 0.f);
        if (gy >= 0 && gy < Hn && gx >= 0 && gx < Wn) {
            const int g = gy * Wn + gx;
            float q0, q1, q2, q3;
            if (IN_PACKED) {
                const float4 q = QinPacked[b * HWn + g];
                q0 = q.x; q1 = q.y; q2 = q.z; q3 = q.w;
            } else {
                const float* Qb = QinPlanar + b * CHWn;
                q0 = Qb[g];
                q1 = Qb[g + HWn];
                q2 = Qb[g + 2 * HWn];
                q3 = Qb[g + 3 * HWn];
            }
            const float mx = fmaxf(fmaxf(q0, q1), fmaxf(q2, q3));
            float p0 = ex2((q0 - mx) * L2Ef);
            float p1 = ex2((q1 - mx) * L2Ef);
            float p2 = ex2((q2 - mx) * L2Ef);
            float p3 = ex2((q3 - mx) * L2Ef);
            const float inv = __fdividef(1.0f, p0 + p1 + p2 + p3);
            sq.x = p0 * inv; sq.y = p1 * inv; sq.z = p2 * inv; sq.w = p3 * inv;
        }
        sQ[i] = sq;
    }

    // Uniform parameters
    const float wa0 = wapp[0], wa1 = wapp[1], wa2 = wapp[2], wa3 = wapp[3];
    const float ws0 = wsmo[0], ws1 = wsmo[1], ws2 = wsmo[2], ws3 = wsmo[3];
    const float c00 = compat[0],  c01 = compat[1],  c02 = compat[2],  c03 = compat[3];
    const float c10 = compat[4],  c11 = compat[5],  c12 = compat[6],  c13 = compat[7];
    const float c20 = compat[8],  c21 = compat[9],  c22 = compat[10], c23 = compat[11];
    const float c30 = compat[12], c31 = compat[13], c32 = compat[14], c33 = compat[15];

    __syncthreads();

    const unsigned long long w1p = pk2(W1, W1);
    const unsigned long long w2p = pk2(W2, W2);
    const unsigned long long w4p = pk2(W4, W4);
    const unsigned long long w5p = pk2(W5, W5);

    // ---- Phase 2 ----
    #pragma unroll
    for (int k = 0; k < (TX * TY) / NTHREADS; ++k) {
        const int p  = tid + k * NTHREADS;
        const int ty = p / TX;
        const int tx = p - ty * TX;
        const int base = (ty + 1) * HX + (tx + 2);

        const int g   = (ty0 + ty) * Wn + (tx0 + tx);
        const int pix = b * HWn + g;
        const int gg  = b * CHWn + g;

        // Issue long-latency loads early
        const unsigned char alive = g_alive[pix];
        const float u0 = unary[gg];
        const float u1 = unary[gg + HWn];
        const float u2 = unary[gg + 2 * HWn];
        const float u3 = unary[gg + 3 * HWn];

        const int offs[14] = {
            -HX - 2, -HX - 1, -HX, -HX + 1, -HX + 2,
                  -2,      -1,           1,       2,
             HX - 2,  HX - 1,  HX,  HX + 1,  HX + 2
        };
        const unsigned long long wtp[14] = {
            w5p, w2p, w1p, w2p, w5p,
            w4p, w1p, w1p, w4p,
            w5p, w2p, w1p, w2p, w5p
        };

        unsigned long long s01 = 0ull, s23 = 0ull;
        unsigned long long a01 = 0ull, a23 = 0ull;

        // Common path: smoothness conv only (Q taps, no geometry, no exp)
        #pragma unroll
        for (int t = 0; t < 14; ++t) {
            const ulonglong2 q2 =
                *reinterpret_cast<const ulonglong2*>(&sQ[base + offs[t]]);
            s01 = ffma2(wtp[t], q2.x, s01);
            s23 = ffma2(wtp[t], q2.y, s23);
        }

        // Rare path (~0.3% pixels): appearance from precomputed betas
        if (alive) {
            const float* __restrict__ bp = g_beta + pix * 14;
            #pragma unroll
            for (int t = 0; t < 14; ++t) {
                const float bm = bp[t];
                const ulonglong2 q2 =
                    *reinterpret_cast<const ulonglong2*>(&sQ[base + offs[t]]);
                const unsigned long long bm2 = pk2(bm, bm);
                a01 = ffma2(bm2, q2.x, a01);
                a23 = ffma2(bm2, q2.y, a23);
            }
        }

        float s0, s1, s2, s3, a0, a1, a2, a3;
        upk2(s01, s0, s1); upk2(s23, s2, s3);
        upk2(a01, a0, a1); upk2(a23, a2, a3);

        // weighted_k = s * (ws + wa * exp_app)   (center mask folded into alive)
        const float wk0 = s0 * fmaf(wa0, a0, ws0);
        const float wk1 = s1 * fmaf(wa1, a1, ws1);
        const float wk2 = s2 * fmaf(wa2, a2, ws2);
        const float wk3 = s3 * fmaf(wa3, a3, ws3);

        const float pw0 = c00 * wk0 + c01 * wk1 + c02 * wk2 + c03 * wk3;
        const float pw1 = c10 * wk0 + c11 * wk1 + c12 * wk2 + c13 * wk3;
        const float pw2 = c20 * wk0 + c21 * wk1 + c22 * wk2 + c23 * wk3;
        const float pw3 = c30 * wk0 + c31 * wk1 + c32 * wk2 + c33 * wk3;

        if (OUT_PACKED) {
            OutPacked[b * HWn + g] = make_float4(u0 - pw0, u1 - pw1, u2 - pw2, u3 - pw3);
        } else {
            OutPlanar[gg]           = u0 - pw0;
            OutPlanar[gg + HWn]     = u1 - pw1;
            OutPlanar[gg + 2 * HWn] = u2 - pw2;
            OutPlanar[gg + 3 * HWn] = u3 - pw3;
        }
    }
}

extern "C" void kernel_launch(void* const* d_in, const int* in_sizes, int n_in,
                              void* d_out, int out_size)
{
    const float* unary  = (const float*)d_in[0];
    const float* xyz    = (const float*)d_in[1];
    const float* mask   = (const float*)d_in[2];
    const float* wapp   = (const float*)d_in[3];
    const float* wsmo   = (const float*)d_in[4];
    const float* compat = (const float*)d_in[5];
    float* out = (float*)d_out;

    float4* sA = nullptr;
    float4* sB = nullptr;
    cudaGetSymbolAddress((void**)&sA, g_scratchA);
    cudaGetSymbolAddress((void**)&sB, g_scratchB);

    dim3 grid(Wn / TX, Hn / TY, Bn);
    dim3 block(NTHREADS);

    // Setup: alive flags + sparse betas (iteration-invariant)
    crf_setup<<<grid, block>>>(xyz, mask);

    // iter 1: unary(planar) -> scratchA(packed)
    crf_iter<false, true><<<grid, block>>>(unary, nullptr, unary,
                                           wapp, wsmo, compat, nullptr, sA);
    // iter 2: scratchA(packed) -> scratchB(packed)
    crf_iter<true, true><<<grid, block>>>(nullptr, sA, unary,
                                          wapp, wsmo, compat, nullptr, sB);
    // iter 3: scratchB(packed) -> out(planar)
    crf_iter<true, false><<<grid, block>>>(nullptr, sB, unary,
                                           wapp, wsmo, compat, out, nullptr);
}

// round 6
// speedup vs baseline: 1.8719x; 1.1688x over previous
#include <cuda_runtime.h>

// Problem constants
#define Bn 8
#define Hn 64
#define Wn 2048
#define HWn (Hn * Wn)          // 131072
#define CHWn (4 * HWn)         // 524288

// Tile config
#define TX 128
#define TY 8
#define HX (TX + 4)            // 132
#define HY (TY + 2)            // 10
#define HALO (HX * HY)         // 1320
#define NH (HY * TX)           // 1280  (H-pass points: 10 rows x 128 cols)
#define NTHREADS 256

// Separable Gaussian weights: exp(-d^2/(2*0.9^2)) for d=1,2
#define W1 0.53940751f   // d = 1
#define W4 0.08465798f   // d = 2

// C2 = -1/(2*0.015^2) * log2(e)
#define C2f      (-3206.0005353f)
#define NEG2C2f  (6412.0010706f)
#define L2Ef     (1.4426950408889634f)
#define MASK_BIG (1.0e9f)
#define SKIP_THR (-40.0f)      // exp2(-40) ~ 9e-13 -> dead

// Scratch (allocation forbidden -> device globals)
__device__ float4        g_scratchA[Bn * HWn];
__device__ float4        g_scratchB[Bn * HWn];
__device__ unsigned char g_alive[Bn * HWn];
__device__ float         g_beta[Bn * HWn * 14];   // sparse: only alive pixels touched

// ---- packed f32x2 helpers (sm_10x) ----
__device__ __forceinline__ unsigned long long pk2(float lo, float hi) {
    unsigned long long r;
    asm("mov.b64 %0, {%1, %2};" : "=l"(r) : "f"(lo), "f"(hi));
    return r;
}
__device__ __forceinline__ void upk2(unsigned long long v, float& lo, float& hi) {
    asm("mov.b64 {%0, %1}, %2;" : "=f"(lo), "=f"(hi) : "l"(v));
}
__device__ __forceinline__ unsigned long long ffma2(unsigned long long a,
                                                    unsigned long long b,
                                                    unsigned long long c) {
    unsigned long long d;
    asm("fma.rn.f32x2 %0, %1, %2, %3;" : "=l"(d) : "l"(a), "l"(b), "l"(c));
    return d;
}
__device__ __forceinline__ unsigned long long fadd2(unsigned long long a,
                                                    unsigned long long b) {
    unsigned long long d;
    asm("add.rn.f32x2 %0, %1, %2;" : "=l"(d) : "l"(a), "l"(b));
    return d;
}
__device__ __forceinline__ float ex2(float x) {
    float r;
    asm("ex2.approx.ftz.f32 %0, %1;" : "=f"(r) : "f"(x));
    return r;
}

// ============================================================================
// Setup: per-pixel alive flag + (rare) exact beta taps. Iteration-invariant.
// ============================================================================
__global__ __launch_bounds__(NTHREADS)
void crf_setup(const float* __restrict__ xyz,
               const float* __restrict__ mask)
{
    __shared__ float4 sG[HALO];   // (x, y, z, |xyz|^2*C2 + (m-1)*BIG)

    const int b   = blockIdx.z;
    const int ty0 = blockIdx.y * TY;
    const int tx0 = blockIdx.x * TX;
    const int tid = threadIdx.x;

    const float* __restrict__ Xb = xyz  + b * 3 * HWn;
    const float* __restrict__ Mb = mask + b * HWn;

    for (int i = tid; i < HALO; i += NTHREADS) {
        const int hy = i / HX;
        const int hx = i - hy * HX;
        const int gy = ty0 + hy - 1;
        const int gx = tx0 + hx - 2;
        float4 sg = make_float4(0.f, 0.f, 0.f, -MASK_BIG);
        if (gy >= 0 && gy < Hn && gx >= 0 && gx < Wn) {
            const int g = gy * Wn + gx;
            const float x = Xb[g];
            const float y = Xb[g + HWn];
            const float z = Xb[g + 2 * HWn];
            const float m = Mb[g];
            float nrm = x * x;
            nrm = fmaf(y, y, nrm);
            nrm = fmaf(z, z, nrm);
            sg.x = x; sg.y = y; sg.z = z;
            sg.w = fmaf(nrm, C2f, fmaf(m, MASK_BIG, -MASK_BIG));
        }
        sG[i] = sg;
    }
    __syncthreads();

    const int offs[14] = {
        -HX - 2, -HX - 1, -HX, -HX + 1, -HX + 2,
              -2,      -1,           1,       2,
         HX - 2,  HX - 1,  HX,  HX + 1,  HX + 2
    };

    for (int k = 0; k < (TX * TY) / NTHREADS; ++k) {
        const int p  = tid + k * NTHREADS;
        const int ty = p >> 7;
        const int tx = p & (TX - 1);
        const int base = (ty + 1) * HX + (tx + 2);

        const float4 ga = sG[base];
        const float axs = ga.x * NEG2C2f;
        const float ays = ga.y * NEG2C2f;
        const float azs = ga.z * NEG2C2f;
        const float na  = ga.w;

        float maxa = -MASK_BIG;
        #pragma unroll
        for (int t = 0; t < 14; ++t) {
            const float4 gn = sG[base + offs[t]];
            const float arg = fmaf(gn.x, axs,
                              fmaf(gn.y, ays,
                              fmaf(gn.z, azs, gn.w + na)));
            maxa = fmaxf(maxa, arg);
        }

        // alive only if some beta survives AND center unmasked
        const bool alive = (maxa > SKIP_THR) && (na > -1.0e8f);
        const int pix = b * HWn + (ty0 + ty) * Wn + (tx0 + tx);
        g_alive[pix] = alive ? 1 : 0;

        if (alive) {
            #pragma unroll
            for (int t = 0; t < 14; ++t) {
                const float4 gn = sG[base + offs[t]];
                const float arg = fmaf(gn.x, axs,
                                  fmaf(gn.y, ays,
                                  fmaf(gn.z, azs, gn.w + na)));
                g_beta[pix * 14 + t] = ex2(arg);
            }
        }
    }
}

// ============================================================================
// One CRF iteration: softmax + SEPARABLE smoothness conv; sparse appearance.
// ============================================================================
template<bool IN_PACKED, bool OUT_PACKED>
__global__ __launch_bounds__(NTHREADS, 4)
void crf_iter(const float*  __restrict__ QinPlanar,
              const float4* __restrict__ QinPacked,
              const float*  __restrict__ unary,
              const float*  __restrict__ wapp,
              const float*  __restrict__ wsmo,
              const float*  __restrict__ compat,
              float*        __restrict__ OutPlanar,
              float4*       __restrict__ OutPacked)
{
    __shared__ float4 sQ[HALO];       // softmaxed probs (halo)
    __shared__ float4 sH[NH];         // horizontal-pass partials [10][128]

    const int b   = blockIdx.z;
    const int ty0 = blockIdx.y * TY;
    const int tx0 = blockIdx.x * TX;
    const int tid = threadIdx.x;

    // ---- Phase 1: softmax halo tile into smem ----
    for (int i = tid; i < HALO; i += NTHREADS) {
        const int hy = i / HX;
        const int hx = i - hy * HX;
        const int gy = ty0 + hy - 1;
        const int gx = tx0 + hx - 2;
        float4 sq = make_float4(0.f, 0.f, 0.f, 0.f);
        if (gy >= 0 && gy < Hn && gx >= 0 && gx < Wn) {
            const int g = gy * Wn + gx;
            float q0, q1, q2, q3;
            if (IN_PACKED) {
                const float4 q = QinPacked[b * HWn + g];
                q0 = q.x; q1 = q.y; q2 = q.z; q3 = q.w;
            } else {
                const float* Qb = QinPlanar + b * CHWn;
                q0 = Qb[g];
                q1 = Qb[g + HWn];
                q2 = Qb[g + 2 * HWn];
                q3 = Qb[g + 3 * HWn];
            }
            const float mx = fmaxf(fmaxf(q0, q1), fmaxf(q2, q3));
            float p0 = ex2((q0 - mx) * L2Ef);
            float p1 = ex2((q1 - mx) * L2Ef);
            float p2 = ex2((q2 - mx) * L2Ef);
            float p3 = ex2((q3 - mx) * L2Ef);
            const float inv = __fdividef(1.0f, p0 + p1 + p2 + p3);
            sq.x = p0 * inv; sq.y = p1 * inv; sq.z = p2 * inv; sq.w = p3 * inv;
        }
        sQ[i] = sq;
    }
    __syncthreads();

    const unsigned long long w1p = pk2(W1, W1);
    const unsigned long long w4p = pk2(W4, W4);
    const unsigned long long n1p = pk2(-1.0f, -1.0f);

    // ---- Phase 2a: horizontal 5-tap pass -> sH[10][128] ----
    for (int i = tid; i < NH; i += NTHREADS) {
        const int hy = i >> 7;             // 0..9
        const int hx = i & (TX - 1);       // 0..127
        const int c  = hy * HX + (hx + 2); // center in sQ
        const ulonglong2 qm2 = *reinterpret_cast<const ulonglong2*>(&sQ[c - 2]);
        const ulonglong2 qm1 = *reinterpret_cast<const ulonglong2*>(&sQ[c - 1]);
        const ulonglong2 qc  = *reinterpret_cast<const ulonglong2*>(&sQ[c]);
        const ulonglong2 qp1 = *reinterpret_cast<const ulonglong2*>(&sQ[c + 1]);
        const ulonglong2 qp2 = *reinterpret_cast<const ulonglong2*>(&sQ[c + 2]);
        ulonglong2 h;
        h.x = ffma2(w4p, fadd2(qm2.x, qp2.x), ffma2(w1p, fadd2(qm1.x, qp1.x), qc.x));
        h.y = ffma2(w4p, fadd2(qm2.y, qp2.y), ffma2(w1p, fadd2(qm1.y, qp1.y), qc.y));
        *reinterpret_cast<ulonglong2*>(&sH[i]) = h;
    }

    // Uniform parameters
    const float wa0 = wapp[0], wa1 = wapp[1], wa2 = wapp[2], wa3 = wapp[3];
    const float ws0 = wsmo[0], ws1 = wsmo[1], ws2 = wsmo[2], ws3 = wsmo[3];
    const float c00 = compat[0],  c01 = compat[1],  c02 = compat[2],  c03 = compat[3];
    const float c10 = compat[4],  c11 = compat[5],  c12 = compat[6],  c13 = compat[7];
    const float c20 = compat[8],  c21 = compat[9],  c22 = compat[10], c23 = compat[11];
    const float c30 = compat[12], c31 = compat[13], c32 = compat[14], c33 = compat[15];

    __syncthreads();

    // ---- Phase 2b: vertical 3-tap pass - center + appearance + epilogue ----
    for (int k = 0; k < (TX * TY) / NTHREADS; ++k) {
        const int p  = tid + k * NTHREADS;
        const int ty = p >> 7;
        const int tx = p & (TX - 1);

        const int hc   = (ty + 1) * TX + tx;        // center in sH
        const int base = (ty + 1) * HX + (tx + 2);  // center in sQ

        const int g   = (ty0 + ty) * Wn + (tx0 + tx);
        const int pix = b * HWn + g;
        const int gg  = b * CHWn + g;

        const unsigned char alive = g_alive[pix];

        const ulonglong2 hm = *reinterpret_cast<const ulonglong2*>(&sH[hc - TX]);
        const ulonglong2 h0 = *reinterpret_cast<const ulonglong2*>(&sH[hc]);
        const ulonglong2 hp = *reinterpret_cast<const ulonglong2*>(&sH[hc + TX]);
        const ulonglong2 qc = *reinterpret_cast<const ulonglong2*>(&sQ[base]);

        // S = H0 + W1*(Hm+Hp) - Qc   (center hole)
        unsigned long long s01 = ffma2(n1p, qc.x, ffma2(w1p, fadd2(hm.x, hp.x), h0.x));
        unsigned long long s23 = ffma2(n1p, qc.y, ffma2(w1p, fadd2(hm.y, hp.y), h0.y));

        unsigned long long a01 = 0ull, a23 = 0ull;

        // Rare path (~0.3% pixels): appearance from precomputed betas
        if (alive) {
            const float* __restrict__ bp = g_beta + pix * 14;
            const int offs[14] = {
                -HX - 2, -HX - 1, -HX, -HX + 1, -HX + 2,
                      -2,      -1,           1,       2,
                 HX - 2,  HX - 1,  HX,  HX + 1,  HX + 2
            };
            #pragma unroll
            for (int t = 0; t < 14; ++t) {
                const float bm = bp[t];
                const ulonglong2 q2 =
                    *reinterpret_cast<const ulonglong2*>(&sQ[base + offs[t]]);
                const unsigned long long bm2 = pk2(bm, bm);
                a01 = ffma2(bm2, q2.x, a01);
                a23 = ffma2(bm2, q2.y, a23);
            }
        }

        float s0, s1, s2, s3, a0, a1, a2, a3;
        upk2(s01, s0, s1); upk2(s23, s2, s3);
        upk2(a01, a0, a1); upk2(a23, a2, a3);

        // weighted_k = s * (ws + wa * exp_app)
        const float wk0 = s0 * fmaf(wa0, a0, ws0);
        const float wk1 = s1 * fmaf(wa1, a1, ws1);
        const float wk2 = s2 * fmaf(wa2, a2, ws2);
        const float wk3 = s3 * fmaf(wa3, a3, ws3);

        const float pw0 = c00 * wk0 + c01 * wk1 + c02 * wk2 + c03 * wk3;
        const float pw1 = c10 * wk0 + c11 * wk1 + c12 * wk2 + c13 * wk3;
        const float pw2 = c20 * wk0 + c21 * wk1 + c22 * wk2 + c23 * wk3;
        const float pw3 = c30 * wk0 + c31 * wk1 + c32 * wk2 + c33 * wk3;

        const float u0 = unary[gg];
        const float u1 = unary[gg + HWn];
        const float u2 = unary[gg + 2 * HWn];
        const float u3 = unary[gg + 3 * HWn];

        if (OUT_PACKED) {
            OutPacked[b * HWn + g] = make_float4(u0 - pw0, u1 - pw1, u2 - pw2, u3 - pw3);
        } else {
            OutPlanar[gg]           = u0 - pw0;
            OutPlanar[gg + HWn]     = u1 - pw1;
            OutPlanar[gg + 2 * HWn] = u2 - pw2;
            OutPlanar[gg + 3 * HWn] = u3 - pw3;
        }
    }
}

extern "C" void kernel_launch(void* const* d_in, const int* in_sizes, int n_in,
                              void* d_out, int out_size)
{
    const float* unary  = (const float*)d_in[0];
    const float* xyz    = (const float*)d_in[1];
    const float* mask   = (const float*)d_in[2];
    const float* wapp   = (const float*)d_in[3];
    const float* wsmo   = (const float*)d_in[4];
    const float* compat = (const float*)d_in[5];
    float* out = (float*)d_out;

    float4* sA = nullptr;
    float4* sB = nullptr;
    cudaGetSymbolAddress((void**)&sA, g_scratchA);
    cudaGetSymbolAddress((void**)&sB, g_scratchB);

    dim3 grid(Wn / TX, Hn / TY, Bn);
    dim3 block(NTHREADS);

    // Setup: alive flags + sparse betas (iteration-invariant)
    crf_setup<<<grid, block>>>(xyz, mask);

    // iter 1: unary(planar) -> scratchA(packed)
    crf_iter<false, true><<<grid, block>>>(unary, nullptr, unary,
                                           wapp, wsmo, compat, nullptr, sA);
    // iter 2: scratchA(packed) -> scratchB(packed)
    crf_iter<true, true><<<grid, block>>>(nullptr, sA, unary,
                                          wapp, wsmo, compat, nullptr, sB);
    // iter 3: scratchB(packed) -> out(planar)
    crf_iter<true, false><<<grid, block>>>(nullptr, sB, unary,
                                           wapp, wsmo, compat, out, nullptr);
}

// round 7
// speedup vs baseline: 1.9401x; 1.0364x over previous
#include <cuda_runtime.h>

// Problem constants
#define Bn 8
#define Hn 64
#define Wn 2048
#define HWn (Hn * Wn)          // 131072
#define CHWn (4 * HWn)         // 524288

// Fused-kernel tile: 128x8 output, +-6 x / +-3 y halo for 3 iterations
#define TX 128
#define TY 8
#define EX 140
#define EY 14
#define NEXT (EX * EY)         // 1960
#define NTHREADS 256

// Setup-kernel tile (single-iteration halo)
#define SHX (TX + 4)           // 132
#define SHY (TY + 2)           // 10
#define SHALO (SHX * SHY)      // 1320

// Separable Gaussian weights: exp(-d^2/(2*0.9^2)) for d=1,2
#define W1 0.53940751f
#define W4 0.08465798f

// C2 = -1/(2*0.015^2) * log2(e)
#define C2f      (-3206.0005353f)
#define NEG2C2f  (6412.0010706f)
#define L2Ef     (1.4426950408889634f)
#define MASK_BIG (1.0e9f)
#define SKIP_THR (-40.0f)      // exp2(-40) ~ 9e-13 -> dead

#define SMEM_BYTES (2 * NEXT * (int)sizeof(float4))   // 62720

// Iteration-invariant appearance data (allocation forbidden -> device globals)
__device__ unsigned char g_alive[Bn * HWn];
__device__ float         g_beta[Bn * HWn * 14];   // only alive pixels touched

// ---- packed f32x2 helpers (sm_10x) ----
__device__ __forceinline__ unsigned long long pk2(float lo, float hi) {
    unsigned long long r;
    asm("mov.b64 %0, {%1, %2};" : "=l"(r) : "f"(lo), "f"(hi));
    return r;
}
__device__ __forceinline__ void upk2(unsigned long long v, float& lo, float& hi) {
    asm("mov.b64 {%0, %1}, %2;" : "=f"(lo), "=f"(hi) : "l"(v));
}
__device__ __forceinline__ unsigned long long ffma2(unsigned long long a,
                                                    unsigned long long b,
                                                    unsigned long long c) {
    unsigned long long d;
    asm("fma.rn.f32x2 %0, %1, %2, %3;" : "=l"(d) : "l"(a), "l"(b), "l"(c));
    return d;
}
__device__ __forceinline__ unsigned long long fadd2(unsigned long long a,
                                                    unsigned long long b) {
    unsigned long long d;
    asm("add.rn.f32x2 %0, %1, %2;" : "=l"(d) : "l"(a), "l"(b));
    return d;
}
__device__ __forceinline__ float ex2(float x) {
    float r;
    asm("ex2.approx.ftz.f32 %0, %1;" : "=f"(r) : "f"(x));
    return r;
}

__device__ __forceinline__ float4 softmax4(float4 q) {
    const float mx = fmaxf(fmaxf(q.x, q.y), fmaxf(q.z, q.w));
    const float p0 = ex2((q.x - mx) * L2Ef);
    const float p1 = ex2((q.y - mx) * L2Ef);
    const float p2 = ex2((q.z - mx) * L2Ef);
    const float p3 = ex2((q.w - mx) * L2Ef);
    const float inv = __fdividef(1.0f, p0 + p1 + p2 + p3);
    return make_float4(p0 * inv, p1 * inv, p2 * inv, p3 * inv);
}

// ============================================================================
// Setup: per-pixel alive flag + (rare) exact beta taps. Iteration-invariant.
// ============================================================================
__global__ __launch_bounds__(NTHREADS)
void crf_setup(const float* __restrict__ xyz,
               const float* __restrict__ mask)
{
    __shared__ float4 sG[SHALO];

    const int b   = blockIdx.z;
    const int ty0 = blockIdx.y * TY;
    const int tx0 = blockIdx.x * TX;
    const int tid = threadIdx.x;

    const float* __restrict__ Xb = xyz  + b * 3 * HWn;
    const float* __restrict__ Mb = mask + b * HWn;

    for (int i = tid; i < SHALO; i += NTHREADS) {
        const int hy = i / SHX;
        const int hx = i - hy * SHX;
        const int gy = ty0 + hy - 1;
        const int gx = tx0 + hx - 2;
        float4 sg = make_float4(0.f, 0.f, 0.f, -MASK_BIG);
        if (gy >= 0 && gy < Hn && gx >= 0 && gx < Wn) {
            const int g = gy * Wn + gx;
            const float x = Xb[g];
            const float y = Xb[g + HWn];
            const float z = Xb[g + 2 * HWn];
            const float m = Mb[g];
            float nrm = x * x;
            nrm = fmaf(y, y, nrm);
            nrm = fmaf(z, z, nrm);
            sg.x = x; sg.y = y; sg.z = z;
            sg.w = fmaf(nrm, C2f, fmaf(m, MASK_BIG, -MASK_BIG));
        }
        sG[i] = sg;
    }
    __syncthreads();

    const int offs[14] = {
        -SHX - 2, -SHX - 1, -SHX, -SHX + 1, -SHX + 2,
               -2,       -1,            1,        2,
         SHX - 2,  SHX - 1,  SHX,  SHX + 1,  SHX + 2
    };

    for (int k = 0; k < (TX * TY) / NTHREADS; ++k) {
        const int p  = tid + k * NTHREADS;
        const int ty = p >> 7;
        const int tx = p & (TX - 1);
        const int base = (ty + 1) * SHX + (tx + 2);

        const float4 ga = sG[base];
        const float axs = ga.x * NEG2C2f;
        const float ays = ga.y * NEG2C2f;
        const float azs = ga.z * NEG2C2f;
        const float na  = ga.w;

        float maxa = -MASK_BIG;
        #pragma unroll
        for (int t = 0; t < 14; ++t) {
            const float4 gn = sG[base + offs[t]];
            const float arg = fmaf(gn.x, axs,
                              fmaf(gn.y, ays,
                              fmaf(gn.z, azs, gn.w + na)));
            maxa = fmaxf(maxa, arg);
        }

        const bool alive = (maxa > SKIP_THR) && (na > -1.0e8f);
        const int pix = b * HWn + (ty0 + ty) * Wn + (tx0 + tx);
        g_alive[pix] = alive ? 1 : 0;

        if (alive) {
            #pragma unroll
            for (int t = 0; t < 14; ++t) {
                const float4 gn = sG[base + offs[t]];
                const float arg = fmaf(gn.x, axs,
                                  fmaf(gn.y, ays,
                                  fmaf(gn.z, azs, gn.w + na)));
                g_beta[pix * 14 + t] = ex2(arg);
            }
        }
    }
}

// ============================================================================
// One in-smem CRF iteration within the fused kernel.
// Region shrinks with IT: H-pass rows [IT, 14-IT), cols [2IT+2, 138-2IT);
// update rows [IT+1, 13-IT), same cols.
// ============================================================================
template<int IT, bool LAST>
__device__ __forceinline__ void crf_do_iter(
    float4* __restrict__ sQ, float4* __restrict__ sH,
    const int b, const int ty0, const int tx0, const int tid,
    const float* __restrict__ unary,
    const float4 wa, const float4 ws,
    const float4 cr0, const float4 cr1, const float4 cr2, const float4 cr3,
    float* __restrict__ out)
{
    constexpr int HR0 = IT,        HR1 = EY - IT;
    constexpr int HC0 = 2 * IT + 2, HC1 = EX - 2 - 2 * IT;
    constexpr int HWID = HC1 - HC0;                       // 136 / 132 / 128
    constexpr int HCOUNT = (HR1 - HR0) * HWID;
    constexpr int UR0 = IT + 1,    UR1 = EY - 1 - IT;
    constexpr int UCOUNT = (UR1 - UR0) * HWID;            // 1632 / 1320 / 1024
    constexpr int NPX = (UCOUNT + NTHREADS - 1) / NTHREADS;

    const unsigned long long w1p = pk2(W1, W1);
    const unsigned long long w4p = pk2(W4, W4);
    const unsigned long long n1p = pk2(-1.0f, -1.0f);

    // ---- Horizontal 5-tap pass ----
    for (int j = tid; j < HCOUNT; j += NTHREADS) {
        const int row = HR0 + j / HWID;
        const int col = HC0 + j % HWID;
        const int c = row * EX + col;
        const ulonglong2 qm2 = *reinterpret_cast<const ulonglong2*>(&sQ[c - 2]);
        const ulonglong2 qm1 = *reinterpret_cast<const ulonglong2*>(&sQ[c - 1]);
        const ulonglong2 qc  = *reinterpret_cast<const ulonglong2*>(&sQ[c]);
        const ulonglong2 qp1 = *reinterpret_cast<const ulonglong2*>(&sQ[c + 1]);
        const ulonglong2 qp2 = *reinterpret_cast<const ulonglong2*>(&sQ[c + 2]);
        ulonglong2 h;
        h.x = ffma2(w4p, fadd2(qm2.x, qp2.x), ffma2(w1p, fadd2(qm1.x, qp1.x), qc.x));
        h.y = ffma2(w4p, fadd2(qm2.y, qp2.y), ffma2(w1p, fadd2(qm1.y, qp1.y), qc.y));
        *reinterpret_cast<ulonglong2*>(&sH[c]) = h;
    }
    __syncthreads();

    // ---- Vertical 3-tap pass + update ----
    float4 nq[NPX];

    #pragma unroll
    for (int k = 0; k < NPX; ++k) {
        const int j = tid + k * NTHREADS;
        if (j < UCOUNT) {
            const int row = UR0 + j / HWID;
            const int col = HC0 + j % HWID;
            const int c = row * EX + col;
            const int gy = ty0 + row - 3;
            const int gx = tx0 + col - 6;
            float4 r = make_float4(0.f, 0.f, 0.f, 0.f);
            const bool inb = LAST || (gy >= 0 && gy < Hn && gx >= 0 && gx < Wn);
            if (inb) {
                const int g   = gy * Wn + gx;
                const int pix = b * HWn + g;
                const int gg  = b * CHWn + g;

                const unsigned char alive = g_alive[pix];

                const ulonglong2 hm = *reinterpret_cast<const ulonglong2*>(&sH[c - EX]);
                const ulonglong2 h0 = *reinterpret_cast<const ulonglong2*>(&sH[c]);
                const ulonglong2 hp = *reinterpret_cast<const ulonglong2*>(&sH[c + EX]);
                const ulonglong2 qc = *reinterpret_cast<const ulonglong2*>(&sQ[c]);

                // S = H0 + W1*(Hm+Hp) - Qc  (center hole)
                unsigned long long s01 = ffma2(n1p, qc.x, ffma2(w1p, fadd2(hm.x, hp.x), h0.x));
                unsigned long long s23 = ffma2(n1p, qc.y, ffma2(w1p, fadd2(hm.y, hp.y), h0.y));

                unsigned long long a01 = 0ull, a23 = 0ull;
                if (alive) {
                    const float* __restrict__ bp = g_beta + pix * 14;
                    const int offs[14] = {
                        -EX - 2, -EX - 1, -EX, -EX + 1, -EX + 2,
                              -2,      -1,           1,       2,
                         EX - 2,  EX - 1,  EX,  EX + 1,  EX + 2
                    };
                    #pragma unroll
                    for (int t = 0; t < 14; ++t) {
                        const float bm = bp[t];
                        const ulonglong2 q2 =
                            *reinterpret_cast<const ulonglong2*>(&sQ[c + offs[t]]);
                        const unsigned long long bm2 = pk2(bm, bm);
                        a01 = ffma2(bm2, q2.x, a01);
                        a23 = ffma2(bm2, q2.y, a23);
                    }
                }

                float s0, s1, s2, s3, a0, a1, a2, a3;
                upk2(s01, s0, s1); upk2(s23, s2, s3);
                upk2(a01, a0, a1); upk2(a23, a2, a3);

                const float wk0 = s0 * fmaf(wa.x, a0, ws.x);
                const float wk1 = s1 * fmaf(wa.y, a1, ws.y);
                const float wk2 = s2 * fmaf(wa.z, a2, ws.z);
                const float wk3 = s3 * fmaf(wa.w, a3, ws.w);

                const float pw0 = cr0.x * wk0 + cr0.y * wk1 + cr0.z * wk2 + cr0.w * wk3;
                const float pw1 = cr1.x * wk0 + cr1.y * wk1 + cr1.z * wk2 + cr1.w * wk3;
                const float pw2 = cr2.x * wk0 + cr2.y * wk1 + cr2.z * wk2 + cr2.w * wk3;
                const float pw3 = cr3.x * wk0 + cr3.y * wk1 + cr3.z * wk2 + cr3.w * wk3;

                r.x = unary[gg]           - pw0;
                r.y = unary[gg + HWn]     - pw1;
                r.z = unary[gg + 2 * HWn] - pw2;
                r.w = unary[gg + 3 * HWn] - pw3;

                if (LAST) {
                    out[gg]           = r.x;
                    out[gg + HWn]     = r.y;
                    out[gg + 2 * HWn] = r.z;
                    out[gg + 3 * HWn] = r.w;
                }
            }
            if (!LAST) nq[k] = r;
        }
    }

    // ---- Writeback: softmax(newQ) into sQ for next iteration ----
    if (!LAST) {
        __syncthreads();
        #pragma unroll
        for (int k = 0; k < NPX; ++k) {
            const int j = tid + k * NTHREADS;
            if (j < UCOUNT) {
                const int row = UR0 + j / HWID;
                const int col = HC0 + j % HWID;
                const int gy = ty0 + row - 3;
                const int gx = tx0 + col - 6;
                const bool inb = (gy >= 0 && gy < Hn && gx >= 0 && gx < Wn);
                sQ[row * EX + col] = inb ? softmax4(nq[k])
                                         : make_float4(0.f, 0.f, 0.f, 0.f);
            }
        }
        __syncthreads();
    }
}

// ============================================================================
// Fused kernel: all 3 CRF iterations with Q resident in shared memory.
// ============================================================================
__global__ __launch_bounds__(NTHREADS, 3)
void crf_fused(const float* __restrict__ unary,
               const float* __restrict__ wapp,
               const float* __restrict__ wsmo,
               const float* __restrict__ compat,
               float*       __restrict__ out)
{
    extern __shared__ float4 smem[];
    float4* sQ = smem;          // [NEXT]
    float4* sH = smem + NEXT;   // [NEXT]

    const int b   = blockIdx.z;
    const int ty0 = blockIdx.y * TY;
    const int tx0 = blockIdx.x * TX;
    const int tid = threadIdx.x;

    // Uniform parameters
    const float4 wa  = make_float4(wapp[0], wapp[1], wapp[2], wapp[3]);
    const float4 ws  = make_float4(wsmo[0], wsmo[1], wsmo[2], wsmo[3]);
    const float4 cr0 = make_float4(compat[0],  compat[1],  compat[2],  compat[3]);
    const float4 cr1 = make_float4(compat[4],  compat[5],  compat[6],  compat[7]);
    const float4 cr2 = make_float4(compat[8],  compat[9],  compat[10], compat[11]);
    const float4 cr3 = make_float4(compat[12], compat[13], compat[14], compat[15]);

    // ---- Phase 0: softmax(unary) over the full 140x14 extended tile ----
    for (int i = tid; i < NEXT; i += NTHREADS) {
        const int row = i / EX;
        const int col = i - row * EX;
        const int gy = ty0 + row - 3;
        const int gx = tx0 + col - 6;
        float4 q = make_float4(0.f, 0.f, 0.f, 0.f);
        if (gy >= 0 && gy < Hn && gx >= 0 && gx < Wn) {
            const int gg = b * CHWn + gy * Wn + gx;
            q = softmax4(make_float4(unary[gg],
                                     unary[gg + HWn],
                                     unary[gg + 2 * HWn],
                                     unary[gg + 3 * HWn]));
        }
        sQ[i] = q;
    }
    __syncthreads();

    crf_do_iter<0, false>(sQ, sH, b, ty0, tx0, tid, unary, wa, ws, cr0, cr1, cr2, cr3, out);
    crf_do_iter<1, false>(sQ, sH, b, ty0, tx0, tid, unary, wa, ws, cr0, cr1, cr2, cr3, out);
    crf_do_iter<2, true >(sQ, sH, b, ty0, tx0, tid, unary, wa, ws, cr0, cr1, cr2, cr3, out);
}

extern "C" void kernel_launch(void* const* d_in, const int* in_sizes, int n_in,
                              void* d_out, int out_size)
{
    const float* unary  = (const float*)d_in[0];
    const float* xyz    = (const float*)d_in[1];
    const float* mask   = (const float*)d_in[2];
    const float* wapp   = (const float*)d_in[3];
    const float* wsmo   = (const float*)d_in[4];
    const float* compat = (const float*)d_in[5];
    float* out = (float*)d_out;

    cudaFuncSetAttribute(crf_fused, cudaFuncAttributeMaxDynamicSharedMemorySize,
                         SMEM_BYTES);

    dim3 grid(Wn / TX, Hn / TY, Bn);
    dim3 block(NTHREADS);

    crf_setup<<<grid, block>>>(xyz, mask);
    crf_fused<<<grid, block, SMEM_BYTES>>>(unary, wapp, wsmo, compat, out);
}

// round 8
// speedup vs baseline: 2.1176x; 1.0915x over previous
#include <cuda_runtime.h>

// Problem constants
#define Bn 8
#define Hn 64
#define Wn 2048
#define HWn (Hn * Wn)          // 131072
#define CHWn (4 * HWn)         // 524288

// Fused-kernel tile: 128x16 output, +-6 x / +-3 y halo for 3 iterations
#define TX 128
#define TY 16
#define EX 140
#define EY 22
#define NEXT (EX * EY)         // 3080
#define NTHREADS 512

// Setup-kernel tile (single-iteration halo)
#define STY 8
#define SNT 256
#define SHX (TX + 4)           // 132
#define SHY (STY + 2)          // 10
#define SHALO (SHX * SHY)      // 1320

// Separable Gaussian weights: exp(-d^2/(2*0.9^2)) for d=1,2
#define W1 0.53940751f
#define W4 0.08465798f

// C2 = -1/(2*0.015^2) * log2(e)
#define C2f      (-3206.0005353f)
#define NEG2C2f  (6412.0010706f)
#define L2Ef     (1.4426950408889634f)
#define MASK_BIG (1.0e9f)
#define SKIP_THR (-40.0f)      // exp2(-40) ~ 9e-13 -> dead

#define SMEM_BYTES (2 * NEXT * (int)sizeof(float4))   // 98560

// Iteration-invariant appearance data (allocation forbidden -> device globals)
__device__ unsigned char g_alive[Bn * HWn];
__device__ float         g_beta[Bn * HWn * 14];   // only alive pixels touched

// ---- packed f32x2 helpers (sm_10x) ----
__device__ __forceinline__ unsigned long long pk2(float lo, float hi) {
    unsigned long long r;
    asm("mov.b64 %0, {%1, %2};" : "=l"(r) : "f"(lo), "f"(hi));
    return r;
}
__device__ __forceinline__ void upk2(unsigned long long v, float& lo, float& hi) {
    asm("mov.b64 {%0, %1}, %2;" : "=f"(lo), "=f"(hi) : "l"(v));
}
__device__ __forceinline__ unsigned long long ffma2(unsigned long long a,
                                                    unsigned long long b,
                                                    unsigned long long c) {
    unsigned long long d;
    asm("fma.rn.f32x2 %0, %1, %2, %3;" : "=l"(d) : "l"(a), "l"(b), "l"(c));
    return d;
}
__device__ __forceinline__ unsigned long long fadd2(unsigned long long a,
                                                    unsigned long long b) {
    unsigned long long d;
    asm("add.rn.f32x2 %0, %1, %2;" : "=l"(d) : "l"(a), "l"(b));
    return d;
}
__device__ __forceinline__ float ex2(float x) {
    float r;
    asm("ex2.approx.ftz.f32 %0, %1;" : "=f"(r) : "f"(x));
    return r;
}

__device__ __forceinline__ float4 softmax4(float4 q) {
    const float mx = fmaxf(fmaxf(q.x, q.y), fmaxf(q.z, q.w));
    const float p0 = ex2((q.x - mx) * L2Ef);
    const float p1 = ex2((q.y - mx) * L2Ef);
    const float p2 = ex2((q.z - mx) * L2Ef);
    const float p3 = ex2((q.w - mx) * L2Ef);
    const float inv = __fdividef(1.0f, p0 + p1 + p2 + p3);
    return make_float4(p0 * inv, p1 * inv, p2 * inv, p3 * inv);
}

// ============================================================================
// Setup: per-pixel alive flag + (rare) exact beta taps. Iteration-invariant.
// ============================================================================
__global__ __launch_bounds__(SNT)
void crf_setup(const float* __restrict__ xyz,
               const float* __restrict__ mask)
{
    __shared__ float4 sG[SHALO];

    const int b   = blockIdx.z;
    const int ty0 = blockIdx.y * STY;
    const int tx0 = blockIdx.x * TX;
    const int tid = threadIdx.x;

    const float* __restrict__ Xb = xyz  + b * 3 * HWn;
    const float* __restrict__ Mb = mask + b * HWn;

    for (int i = tid; i < SHALO; i += SNT) {
        const int hy = i / SHX;
        const int hx = i - hy * SHX;
        const int gy = ty0 + hy - 1;
        const int gx = tx0 + hx - 2;
        float4 sg = make_float4(0.f, 0.f, 0.f, -MASK_BIG);
        if (gy >= 0 && gy < Hn && gx >= 0 && gx < Wn) {
            const int g = gy * Wn + gx;
            const float x = Xb[g];
            const float y = Xb[g + HWn];
            const float z = Xb[g + 2 * HWn];
            const float m = Mb[g];
            float nrm = x * x;
            nrm = fmaf(y, y, nrm);
            nrm = fmaf(z, z, nrm);
            sg.x = x; sg.y = y; sg.z = z;
            sg.w = fmaf(nrm, C2f, fmaf(m, MASK_BIG, -MASK_BIG));
        }
        sG[i] = sg;
    }
    __syncthreads();

    const int offs[14] = {
        -SHX - 2, -SHX - 1, -SHX, -SHX + 1, -SHX + 2,
               -2,       -1,            1,        2,
         SHX - 2,  SHX - 1,  SHX,  SHX + 1,  SHX + 2
    };

    for (int k = 0; k < (TX * STY) / SNT; ++k) {
        const int p  = tid + k * SNT;
        const int ty = p >> 7;
        const int tx = p & (TX - 1);
        const int base = (ty + 1) * SHX + (tx + 2);

        const float4 ga = sG[base];
        const float axs = ga.x * NEG2C2f;
        const float ays = ga.y * NEG2C2f;
        const float azs = ga.z * NEG2C2f;
        const float na  = ga.w;

        float maxa = -MASK_BIG;
        #pragma unroll
        for (int t = 0; t < 14; ++t) {
            const float4 gn = sG[base + offs[t]];
            const float arg = fmaf(gn.x, axs,
                              fmaf(gn.y, ays,
                              fmaf(gn.z, azs, gn.w + na)));
            maxa = fmaxf(maxa, arg);
        }

        const bool alive = (maxa > SKIP_THR) && (na > -1.0e8f);
        const int pix = b * HWn + (ty0 + ty) * Wn + (tx0 + tx);
        g_alive[pix] = alive ? 1 : 0;

        if (alive) {
            #pragma unroll
            for (int t = 0; t < 14; ++t) {
                const float4 gn = sG[base + offs[t]];
                const float arg = fmaf(gn.x, axs,
                                  fmaf(gn.y, ays,
                                  fmaf(gn.z, azs, gn.w + na)));
                g_beta[pix * 14 + t] = ex2(arg);
            }
        }
    }
}

// ============================================================================
// One in-smem CRF iteration within the fused kernel.
// Region shrinks with IT: H-pass rows [IT, EY-IT), cols [2IT+2, 138-2IT);
// update rows [IT+1, EY-1-IT), same cols.
// ============================================================================
template<int IT, bool LAST>
__device__ __forceinline__ void crf_do_iter(
    float4* __restrict__ sQ, float4* __restrict__ sH,
    const int b, const int ty0, const int tx0, const int tid,
    const float* __restrict__ unary,
    const float4 wa, const float4 ws,
    const float4 cr0, const float4 cr1, const float4 cr2, const float4 cr3,
    float* __restrict__ out)
{
    constexpr int HR0 = IT,         HR1 = EY - IT;
    constexpr int HC0 = 2 * IT + 2, HC1 = EX - 2 - 2 * IT;
    constexpr int HWID = HC1 - HC0;                       // 136 / 132 / 128
    constexpr int HCOUNT = (HR1 - HR0) * HWID;
    constexpr int UR0 = IT + 1,     UR1 = EY - 1 - IT;
    constexpr int UCOUNT = (UR1 - UR0) * HWID;            // 2720 / 2376 / 2048
    constexpr int NPX = (UCOUNT + NTHREADS - 1) / NTHREADS;

    const unsigned long long w1p = pk2(W1, W1);
    const unsigned long long w4p = pk2(W4, W4);
    const unsigned long long n1p = pk2(-1.0f, -1.0f);

    // ---- Horizontal 5-tap pass ----
    for (int j = tid; j < HCOUNT; j += NTHREADS) {
        const int row = HR0 + j / HWID;
        const int col = HC0 + j % HWID;
        const int c = row * EX + col;
        const ulonglong2 qm2 = *reinterpret_cast<const ulonglong2*>(&sQ[c - 2]);
        const ulonglong2 qm1 = *reinterpret_cast<const ulonglong2*>(&sQ[c - 1]);
        const ulonglong2 qc  = *reinterpret_cast<const ulonglong2*>(&sQ[c]);
        const ulonglong2 qp1 = *reinterpret_cast<const ulonglong2*>(&sQ[c + 1]);
        const ulonglong2 qp2 = *reinterpret_cast<const ulonglong2*>(&sQ[c + 2]);
        ulonglong2 h;
        h.x = ffma2(w4p, fadd2(qm2.x, qp2.x), ffma2(w1p, fadd2(qm1.x, qp1.x), qc.x));
        h.y = ffma2(w4p, fadd2(qm2.y, qp2.y), ffma2(w1p, fadd2(qm1.y, qp1.y), qc.y));
        *reinterpret_cast<ulonglong2*>(&sH[c]) = h;
    }
    __syncthreads();

    // ---- Vertical 3-tap pass + update ----
    float4 nq[NPX];

    #pragma unroll
    for (int k = 0; k < NPX; ++k) {
        const int j = tid + k * NTHREADS;
        if (j < UCOUNT) {
            const int row = UR0 + j / HWID;
            const int col = HC0 + j % HWID;
            const int c = row * EX + col;
            const int gy = ty0 + row - 3;
            const int gx = tx0 + col - 6;
            float4 r = make_float4(0.f, 0.f, 0.f, 0.f);
            const bool inb = LAST || (gy >= 0 && gy < Hn && gx >= 0 && gx < Wn);
            if (inb) {
                const int g   = gy * Wn + gx;
                const int pix = b * HWn + g;
                const int gg  = b * CHWn + g;

                const unsigned char alive = g_alive[pix];

                const ulonglong2 hm = *reinterpret_cast<const ulonglong2*>(&sH[c - EX]);
                const ulonglong2 h0 = *reinterpret_cast<const ulonglong2*>(&sH[c]);
                const ulonglong2 hp = *reinterpret_cast<const ulonglong2*>(&sH[c + EX]);
                const ulonglong2 qc = *reinterpret_cast<const ulonglong2*>(&sQ[c]);

                // S = H0 + W1*(Hm+Hp) - Qc  (center hole)
                unsigned long long s01 = ffma2(n1p, qc.x, ffma2(w1p, fadd2(hm.x, hp.x), h0.x));
                unsigned long long s23 = ffma2(n1p, qc.y, ffma2(w1p, fadd2(hm.y, hp.y), h0.y));

                unsigned long long a01 = 0ull, a23 = 0ull;
                if (alive) {
                    const float* __restrict__ bp = g_beta + pix * 14;
                    const int offs[14] = {
                        -EX - 2, -EX - 1, -EX, -EX + 1, -EX + 2,
                              -2,      -1,           1,       2,
                         EX - 2,  EX - 1,  EX,  EX + 1,  EX + 2
                    };
                    #pragma unroll
                    for (int t = 0; t < 14; ++t) {
                        const float bm = bp[t];
                        const ulonglong2 q2 =
                            *reinterpret_cast<const ulonglong2*>(&sQ[c + offs[t]]);
                        const unsigned long long bm2 = pk2(bm, bm);
                        a01 = ffma2(bm2, q2.x, a01);
                        a23 = ffma2(bm2, q2.y, a23);
                    }
                }

                float s0, s1, s2, s3, a0, a1, a2, a3;
                upk2(s01, s0, s1); upk2(s23, s2, s3);
                upk2(a01, a0, a1); upk2(a23, a2, a3);

                const float wk0 = s0 * fmaf(wa.x, a0, ws.x);
                const float wk1 = s1 * fmaf(wa.y, a1, ws.y);
                const float wk2 = s2 * fmaf(wa.z, a2, ws.z);
                const float wk3 = s3 * fmaf(wa.w, a3, ws.w);

                const float pw0 = cr0.x * wk0 + cr0.y * wk1 + cr0.z * wk2 + cr0.w * wk3;
                const float pw1 = cr1.x * wk0 + cr1.y * wk1 + cr1.z * wk2 + cr1.w * wk3;
                const float pw2 = cr2.x * wk0 + cr2.y * wk1 + cr2.z * wk2 + cr2.w * wk3;
                const float pw3 = cr3.x * wk0 + cr3.y * wk1 + cr3.z * wk2 + cr3.w * wk3;

                r.x = unary[gg]           - pw0;
                r.y = unary[gg + HWn]     - pw1;
                r.z = unary[gg + 2 * HWn] - pw2;
                r.w = unary[gg + 3 * HWn] - pw3;

                if (LAST) {
                    out[gg]           = r.x;
                    out[gg + HWn]     = r.y;
                    out[gg + 2 * HWn] = r.z;
                    out[gg + 3 * HWn] = r.w;
                }
            }
            if (!LAST) nq[k] = r;
        }
    }

    // ---- Writeback: softmax(newQ) into sQ for next iteration ----
    if (!LAST) {
        __syncthreads();
        #pragma unroll
        for (int k = 0; k < NPX; ++k) {
            const int j = tid + k * NTHREADS;
            if (j < UCOUNT) {
                const int row = UR0 + j / HWID;
                const int col = HC0 + j % HWID;
                const int gy = ty0 + row - 3;
                const int gx = tx0 + col - 6;
                const bool inb = (gy >= 0 && gy < Hn && gx >= 0 && gx < Wn);
                sQ[row * EX + col] = inb ? softmax4(nq[k])
                                         : make_float4(0.f, 0.f, 0.f, 0.f);
            }
        }
        __syncthreads();
    }
}

// ============================================================================
// Fused kernel: all 3 CRF iterations with Q resident in shared memory.
// ============================================================================
__global__ __launch_bounds__(NTHREADS, 2)
void crf_fused(const float* __restrict__ unary,
               const float* __restrict__ wapp,
               const float* __restrict__ wsmo,
               const float* __restrict__ compat,
               float*       __restrict__ out)
{
    extern __shared__ float4 smem[];
    float4* sQ = smem;          // [NEXT]
    float4* sH = smem + NEXT;   // [NEXT]

    const int b   = blockIdx.z;
    const int ty0 = blockIdx.y * TY;
    const int tx0 = blockIdx.x * TX;
    const int tid = threadIdx.x;

    // Uniform parameters
    const float4 wa  = make_float4(wapp[0], wapp[1], wapp[2], wapp[3]);
    const float4 ws  = make_float4(wsmo[0], wsmo[1], wsmo[2], wsmo[3]);
    const float4 cr0 = make_float4(compat[0],  compat[1],  compat[2],  compat[3]);
    const float4 cr1 = make_float4(compat[4],  compat[5],  compat[6],  compat[7]);
    const float4 cr2 = make_float4(compat[8],  compat[9],  compat[10], compat[11]);
    const float4 cr3 = make_float4(compat[12], compat[13], compat[14], compat[15]);

    // ---- Phase 0: softmax(unary) over the full 140x22 extended tile ----
    for (int i = tid; i < NEXT; i += NTHREADS) {
        const int row = i / EX;
        const int col = i - row * EX;
        const int gy = ty0 + row - 3;
        const int gx = tx0 + col - 6;
        float4 q = make_float4(0.f, 0.f, 0.f, 0.f);
        if (gy >= 0 && gy < Hn && gx >= 0 && gx < Wn) {
            const int gg = b * CHWn + gy * Wn + gx;
            q = softmax4(make_float4(unary[gg],
                                     unary[gg + HWn],
                                     unary[gg + 2 * HWn],
                                     unary[gg + 3 * HWn]));
        }
        sQ[i] = q;
    }
    __syncthreads();

    crf_do_iter<0, false>(sQ, sH, b, ty0, tx0, tid, unary, wa, ws, cr0, cr1, cr2, cr3, out);
    crf_do_iter<1, false>(sQ, sH, b, ty0, tx0, tid, unary, wa, ws, cr0, cr1, cr2, cr3, out);
    crf_do_iter<2, true >(sQ, sH, b, ty0, tx0, tid, unary, wa, ws, cr0, cr1, cr2, cr3, out);
}

extern "C" void kernel_launch(void* const* d_in, const int* in_sizes, int n_in,
                              void* d_out, int out_size)
{
    const float* unary  = (const float*)d_in[0];
    const float* xyz    = (const float*)d_in[1];
    const float* mask   = (const float*)d_in[2];
    const float* wapp   = (const float*)d_in[3];
    const float* wsmo   = (const float*)d_in[4];
    const float* compat = (const float*)d_in[5];
    float* out = (float*)d_out;

    cudaFuncSetAttribute(crf_fused, cudaFuncAttributeMaxDynamicSharedMemorySize,
                         SMEM_BYTES);

    dim3 sgrid(Wn / TX, Hn / STY, Bn);
    crf_setup<<<sgrid, SNT>>>(xyz, mask);

    dim3 grid(Wn / TX, Hn / TY, Bn);
    crf_fused<<<grid, NTHREADS, SMEM_BYTES>>>(unary, wapp, wsmo, compat, out);
}

// round 9
// speedup vs baseline: 2.4930x; 1.1773x over previous
#include <cuda_runtime.h>
#include <cuda_fp16.h>

// Problem constants
#define Bn 8
#define Hn 64
#define Wn 2048
#define HWn (Hn * Wn)          // 131072
#define CHWn (4 * HWn)         // 524288

// Fused-kernel tile: 128x16 output, +-6 x / +-3 y halo for 3 iterations
#define TX 128
#define TY 16
#define EX 140
#define EY 22
#define NEXT (EX * EY)         // 3080
#define NTHREADS 512

// Setup-kernel tile
#define STY 8
#define SNT 256
#define SHX (TX + 4)           // 132
#define SHY (STY + 2)          // 10
#define SHALO (SHX * SHY)      // 1320

// Separable Gaussian weights: exp(-d^2/(2*0.9^2)) for d=1,2
#define W1f 0.53940751f
#define W4f 0.08465798f

// C2 = -1/(2*0.015^2) * log2(e)
#define C2f      (-3206.0005353f)
#define NEG2C2f  (6412.0010706f)
#define L2Ef     (1.4426950408889634f)
#define MASK_BIG (1.0e9f)
#define SKIP_THR (-40.0f)

#define SMEM_BYTES (3 * NEXT * (int)sizeof(uint2))   // 73920

// Iteration-invariant appearance data (allocation forbidden -> device globals)
__device__ unsigned char g_alive[Bn * HWn];
__device__ float         g_beta[Bn * HWn * 14];

// ---- helpers ----
__device__ __forceinline__ float ex2(float x) {
    float r;
    asm("ex2.approx.ftz.f32 %0, %1;" : "=f"(r) : "f"(x));
    return r;
}
__device__ __forceinline__ __half2 u2h(unsigned u) {
    __half2 h;
    *reinterpret_cast<unsigned*>(&h) = u;
    return h;
}
__device__ __forceinline__ unsigned h2u(__half2 h) {
    return *reinterpret_cast<unsigned*>(&h);
}
__device__ __forceinline__ float4 softmax4(float4 q) {
    const float mx = fmaxf(fmaxf(q.x, q.y), fmaxf(q.z, q.w));
    const float p0 = ex2((q.x - mx) * L2Ef);
    const float p1 = ex2((q.y - mx) * L2Ef);
    const float p2 = ex2((q.z - mx) * L2Ef);
    const float p3 = ex2((q.w - mx) * L2Ef);
    const float inv = __fdividef(1.0f, p0 + p1 + p2 + p3);
    return make_float4(p0 * inv, p1 * inv, p2 * inv, p3 * inv);
}

// ============================================================================
// Setup: per-pixel alive flag + (rare) exact beta taps. Iteration-invariant.
// ============================================================================
__global__ __launch_bounds__(SNT)
void crf_setup(const float* __restrict__ xyz,
               const float* __restrict__ mask)
{
    __shared__ float4 sG[SHALO];

    const int b   = blockIdx.z;
    const int ty0 = blockIdx.y * STY;
    const int tx0 = blockIdx.x * TX;
    const int tid = threadIdx.x;

    const float* __restrict__ Xb = xyz  + b * 3 * HWn;
    const float* __restrict__ Mb = mask + b * HWn;

    for (int i = tid; i < SHALO; i += SNT) {
        const int hy = i / SHX;
        const int hx = i - hy * SHX;
        const int gy = ty0 + hy - 1;
        const int gx = tx0 + hx - 2;
        float4 sg = make_float4(0.f, 0.f, 0.f, -MASK_BIG);
        if (gy >= 0 && gy < Hn && gx >= 0 && gx < Wn) {
            const int g = gy * Wn + gx;
            const float x = Xb[g];
            const float y = Xb[g + HWn];
            const float z = Xb[g + 2 * HWn];
            const float m = Mb[g];
            float nrm = x * x;
            nrm = fmaf(y, y, nrm);
            nrm = fmaf(z, z, nrm);
            sg.x = x; sg.y = y; sg.z = z;
            sg.w = fmaf(nrm, C2f, fmaf(m, MASK_BIG, -MASK_BIG));
        }
        sG[i] = sg;
    }
    __syncthreads();

    const int offs[14] = {
        -SHX - 2, -SHX - 1, -SHX, -SHX + 1, -SHX + 2,
               -2,       -1,            1,        2,
         SHX - 2,  SHX - 1,  SHX,  SHX + 1,  SHX + 2
    };

    for (int k = 0; k < (TX * STY) / SNT; ++k) {
        const int p  = tid + k * SNT;
        const int ty = p >> 7;
        const int tx = p & (TX - 1);
        const int base = (ty + 1) * SHX + (tx + 2);

        const float4 ga = sG[base];
        const float axs = ga.x * NEG2C2f;
        const float ays = ga.y * NEG2C2f;
        const float azs = ga.z * NEG2C2f;
        const float na  = ga.w;

        float maxa = -MASK_BIG;
        #pragma unroll
        for (int t = 0; t < 14; ++t) {
            const float4 gn = sG[base + offs[t]];
            const float arg = fmaf(gn.x, axs,
                              fmaf(gn.y, ays,
                              fmaf(gn.z, azs, gn.w + na)));
            maxa = fmaxf(maxa, arg);
        }

        const bool alive = (maxa > SKIP_THR) && (na > -1.0e8f);
        const int pix = b * HWn + (ty0 + ty) * Wn + (tx0 + tx);
        g_alive[pix] = alive ? 1 : 0;

        if (alive) {
            #pragma unroll
            for (int t = 0; t < 14; ++t) {
                const float4 gn = sG[base + offs[t]];
                const float arg = fmaf(gn.x, axs,
                                  fmaf(gn.y, ays,
                                  fmaf(gn.z, azs, gn.w + na)));
                g_beta[pix * 14 + t] = ex2(arg);
            }
        }
    }
}

// ============================================================================
// One in-smem CRF iteration (fp16 storage, half2 math, smem ping-pong).
// ============================================================================
template<int IT, bool LAST>
__device__ __forceinline__ void crf_do_iter(
    const uint2* __restrict__ sQin, uint2* __restrict__ sQout,
    uint2* __restrict__ sH,
    const int b, const int ty0, const int tx0, const int tid,
    const float* __restrict__ unary, float* __restrict__ out,
    const __half2 w1h, const __half2 w4h,
    const __half2 wa01, const __half2 wa23,
    const __half2 ws01, const __half2 ws23,
    const __half2 ccA0, const __half2 ccA1, const __half2 ccA2, const __half2 ccA3,
    const __half2 ccB0, const __half2 ccB1, const __half2 ccB2, const __half2 ccB3)
{
    constexpr int HR0 = IT, HR1 = EY - IT;
    constexpr int HC0 = 2 * IT + 2;
    constexpr int HWID = EX - 4 - 4 * IT;   // 136 / 132 / 128
    constexpr int EXTRA = HWID - 128;       // 8 / 4 / 0
    constexpr int UR0 = IT + 1, UR1 = EY - 1 - IT;

    // ---- Horizontal 5-tap pass (half2) ----
    auto h_point = [&](int c) {
        const uint2 qm2 = sQin[c - 2];
        const uint2 qm1 = sQin[c - 1];
        const uint2 qc  = sQin[c];
        const uint2 qp1 = sQin[c + 1];
        const uint2 qp2 = sQin[c + 2];
        const __half2 h01 = __hfma2(w4h, __hadd2(u2h(qm2.x), u2h(qp2.x)),
                            __hfma2(w1h, __hadd2(u2h(qm1.x), u2h(qp1.x)), u2h(qc.x)));
        const __half2 h23 = __hfma2(w4h, __hadd2(u2h(qm2.y), u2h(qp2.y)),
                            __hfma2(w1h, __hadd2(u2h(qm1.y), u2h(qp1.y)), u2h(qc.y)));
        sH[c] = make_uint2(h2u(h01), h2u(h23));
    };

    {
        const int cx = tid & 127;
        for (int r = HR0 + (tid >> 7); r < HR1; r += NTHREADS >> 7)
            h_point(r * EX + HC0 + cx);
        if (EXTRA > 0) {
            constexpr int SH2 = (EXTRA == 8) ? 3 : 2;
            const int cx2 = 128 + (tid & (EXTRA - 1));
            const int r = HR0 + (tid >> SH2);
            if (r < HR1) h_point(r * EX + HC0 + cx2);
        }
    }
    __syncthreads();

    // ---- Vertical 3-tap + update ----
    auto u_point = [&](int row, int col) {
        const int c  = row * EX + col;
        const int gy = ty0 + row - 3;
        const int gx = tx0 + col - 6;
        if (!LAST) {
            if (gy < 0 || gy >= Hn || gx < 0 || gx >= Wn) {
                sQout[c] = make_uint2(0u, 0u);
                return;
            }
        }
        const int g   = gy * Wn + gx;
        const int pix = b * HWn + g;
        const int gg  = b * CHWn + g;

        const unsigned char alive = g_alive[pix];

        const uint2 hm = sH[c - EX];
        const uint2 h0 = sH[c];
        const uint2 hp = sH[c + EX];
        const uint2 qc = sQin[c];

        // S = H0 + W1*(Hm+Hp) - Qc
        const __half2 s01 = __hsub2(
            __hfma2(w1h, __hadd2(u2h(hm.x), u2h(hp.x)), u2h(h0.x)), u2h(qc.x));
        const __half2 s23 = __hsub2(
            __hfma2(w1h, __hadd2(u2h(hm.y), u2h(hp.y)), u2h(h0.y)), u2h(qc.y));

        __half2 a01 = __float2half2_rn(0.f);
        __half2 a23 = a01;
        if (alive) {
            const float* __restrict__ bp = g_beta + (size_t)pix * 14;
            const int offs[14] = {
                -EX - 2, -EX - 1, -EX, -EX + 1, -EX + 2,
                      -2,      -1,           1,       2,
                 EX - 2,  EX - 1,  EX,  EX + 1,  EX + 2
            };
            #pragma unroll
            for (int t = 0; t < 14; ++t) {
                const __half2 bmh = __float2half2_rn(bp[t]);
                const uint2 q = sQin[c + offs[t]];
                a01 = __hfma2(bmh, u2h(q.x), a01);
                a23 = __hfma2(bmh, u2h(q.y), a23);
            }
        }

        const __half2 wk01 = __hmul2(s01, __hfma2(wa01, a01, ws01));
        const __half2 wk23 = __hmul2(s23, __hfma2(wa23, a23, ws23));

        // pairwise[o] = sum_c compat[o][c] * wk[c]  (transposed-column packing)
        __half2 pw01 = __hmul2(__low2half2(wk01), ccA0);
        pw01 = __hfma2(__high2half2(wk01), ccA1, pw01);
        pw01 = __hfma2(__low2half2(wk23),  ccA2, pw01);
        pw01 = __hfma2(__high2half2(wk23), ccA3, pw01);
        __half2 pw23 = __hmul2(__low2half2(wk01), ccB0);
        pw23 = __hfma2(__high2half2(wk01), ccB1, pw23);
        pw23 = __hfma2(__low2half2(wk23),  ccB2, pw23);
        pw23 = __hfma2(__high2half2(wk23), ccB3, pw23);

        const float2 p01 = __half22float2(pw01);
        const float2 p23 = __half22float2(pw23);

        const float r0 = unary[gg]           - p01.x;
        const float r1 = unary[gg + HWn]     - p01.y;
        const float r2 = unary[gg + 2 * HWn] - p23.x;
        const float r3 = unary[gg + 3 * HWn] - p23.y;

        if (LAST) {
            out[gg]           = r0;
            out[gg + HWn]     = r1;
            out[gg + 2 * HWn] = r2;
            out[gg + 3 * HWn] = r3;
        } else {
            const float4 sm = softmax4(make_float4(r0, r1, r2, r3));
            sQout[c] = make_uint2(h2u(__floats2half2_rn(sm.x, sm.y)),
                                  h2u(__floats2half2_rn(sm.z, sm.w)));
        }
    };

    {
        const int cx = tid & 127;
        for (int r = UR0 + (tid >> 7); r < UR1; r += NTHREADS >> 7)
            u_point(r, HC0 + cx);
        if (EXTRA > 0) {
            constexpr int SH2 = (EXTRA == 8) ? 3 : 2;
            const int cx2 = 128 + (tid & (EXTRA - 1));
            const int r = UR0 + (tid >> SH2);
            if (r < UR1) u_point(r, HC0 + cx2);
        }
    }
    if (!LAST) __syncthreads();
}

// ============================================================================
// Fused kernel: 3 CRF iterations, Q in fp16 smem, ping-pong buffers.
// ============================================================================
__global__ __launch_bounds__(NTHREADS, 3)
void crf_fused(const float* __restrict__ unary,
               const float* __restrict__ wapp,
               const float* __restrict__ wsmo,
               const float* __restrict__ compat,
               float*       __restrict__ out)
{
    extern __shared__ uint2 smem[];
    uint2* sA = smem;
    uint2* sB = smem + NEXT;
    uint2* sH = smem + 2 * NEXT;

    const int b   = blockIdx.z;
    const int ty0 = blockIdx.y * TY;
    const int tx0 = blockIdx.x * TX;
    const int tid = threadIdx.x;

    // Uniform parameters -> packed half2
    const __half2 w1h  = __float2half2_rn(W1f);
    const __half2 w4h  = __float2half2_rn(W4f);
    const __half2 wa01 = __floats2half2_rn(wapp[0], wapp[1]);
    const __half2 wa23 = __floats2half2_rn(wapp[2], wapp[3]);
    const __half2 ws01 = __floats2half2_rn(wsmo[0], wsmo[1]);
    const __half2 ws23 = __floats2half2_rn(wsmo[2], wsmo[3]);
    // column c of compat for outputs (0,1) and (2,3)
    const __half2 ccA0 = __floats2half2_rn(compat[0],  compat[4]);
    const __half2 ccA1 = __floats2half2_rn(compat[1],  compat[5]);
    const __half2 ccA2 = __floats2half2_rn(compat[2],  compat[6]);
    const __half2 ccA3 = __floats2half2_rn(compat[3],  compat[7]);
    const __half2 ccB0 = __floats2half2_rn(compat[8],  compat[12]);
    const __half2 ccB1 = __floats2half2_rn(compat[9],  compat[13]);
    const __half2 ccB2 = __floats2half2_rn(compat[10], compat[14]);
    const __half2 ccB3 = __floats2half2_rn(compat[11], compat[15]);

    // ---- Phase 0: softmax(unary) over the full extended tile -> sA ----
    for (int i = tid; i < NEXT; i += NTHREADS) {
        const int row = i / EX;
        const int col = i - row * EX;
        const int gy = ty0 + row - 3;
        const int gx = tx0 + col - 6;
        uint2 q = make_uint2(0u, 0u);
        if (gy >= 0 && gy < Hn && gx >= 0 && gx < Wn) {
            const int gg = b * CHWn + gy * Wn + gx;
            const float4 sm = softmax4(make_float4(unary[gg],
                                                   unary[gg + HWn],
                                                   unary[gg + 2 * HWn],
                                                   unary[gg + 3 * HWn]));
            q = make_uint2(h2u(__floats2half2_rn(sm.x, sm.y)),
                           h2u(__floats2half2_rn(sm.z, sm.w)));
        }
        sA[i] = q;
    }
    __syncthreads();

    crf_do_iter<0, false>(sA, sB, sH, b, ty0, tx0, tid, unary, out,
                          w1h, w4h, wa01, wa23, ws01, ws23,
                          ccA0, ccA1, ccA2, ccA3, ccB0, ccB1, ccB2, ccB3);
    crf_do_iter<1, false>(sB, sA, sH, b, ty0, tx0, tid, unary, out,
                          w1h, w4h, wa01, wa23, ws01, ws23,
                          ccA0, ccA1, ccA2, ccA3, ccB0, ccB1, ccB2, ccB3);
    crf_do_iter<2, true >(sA, sB, sH, b, ty0, tx0, tid, unary, out,
                          w1h, w4h, wa01, wa23, ws01, ws23,
                          ccA0, ccA1, ccA2, ccA3, ccB0, ccB1, ccB2, ccB3);
}

extern "C" void kernel_launch(void* const* d_in, const int* in_sizes, int n_in,
                              void* d_out, int out_size)
{
    const float* unary  = (const float*)d_in[0];
    const float* xyz    = (const float*)d_in[1];
    const float* mask   = (const float*)d_in[2];
    const float* wapp   = (const float*)d_in[3];
    const float* wsmo   = (const float*)d_in[4];
    const float* compat = (const float*)d_in[5];
    float* out = (float*)d_out;

    cudaFuncSetAttribute(crf_fused, cudaFuncAttributeMaxDynamicSharedMemorySize,
                         SMEM_BYTES);

    dim3 sgrid(Wn / TX, Hn / STY, Bn);
    crf_setup<<<sgrid, SNT>>>(xyz, mask);

    dim3 grid(Wn / TX, Hn / TY, Bn);
    crf_fused<<<grid, NTHREADS, SMEM_BYTES>>>(unary, wapp, wsmo, compat, out);
}